// round 1
// baseline (speedup 1.0000x reference)
#include <cuda_runtime.h>
#include <math.h>
#include <stdint.h>

#define B 4096
#define H 512
#define H3 1536
#define L 41
#define LP 48
#define V 128
#define BOS 2

// ---------------- device scratch (no allocations allowed) ----------------
__device__ float g_h[B * H];
__device__ float g_gh[B * H3];
__device__ float g_gi[B * H3];
__device__ float g_attnsc[B * L];
__device__ float g_aw[B * LP];
__device__ float g_ctx[B * H];
__device__ float g_x[B * H];
__device__ float g_logits[B * V];
__device__ float g_encpad[L * H];
__device__ float g_encpadT[H * LP];
__device__ float g_enc_tab[V * H3];
__device__ float g_attn_tab[V * L];
__device__ float g_comb_tab[V * H];
__device__ float g_scores[B];

// ---------------- generic NT GEMM: C[m,n] = sum_k A[m,k] * W[n,k] ----------------
// BM=128, BN=64, BK=16, 256 threads, 8x4 per thread.
// Requirements: M % 128 == 0, K % 16 == 0, A/W rows 16B-aligned (lda,ldw % 4 == 0).
__global__ void __launch_bounds__(256) gemm_nt(
    int M, int N, int K,
    const float* __restrict__ A, int lda,
    const float* __restrict__ W, int ldw,
    float* __restrict__ C, int ldc,
    const float* __restrict__ bias,
    const float* __restrict__ rowTab, int tabStride,
    const int* __restrict__ tok, int defTok,
    int doRelu)
{
    __shared__ float As[16][128];
    __shared__ float Ws[16][64];
    const int bm = blockIdx.y * 128;
    const int bn = blockIdx.x * 64;
    const int tid = threadIdx.x;
    const int tx = tid & 15;
    const int ty = tid >> 4;

    float acc[8][4];
#pragma unroll
    for (int i = 0; i < 8; i++)
#pragma unroll
        for (int j = 0; j < 4; j++) acc[i][j] = 0.f;

    for (int k0 = 0; k0 < K; k0 += 16) {
        // A tile: 128x16 = 512 float4, 2 per thread
#pragma unroll
        for (int i = 0; i < 2; i++) {
            int flat = tid + i * 256;
            int r = flat >> 2;
            int c4 = (flat & 3) << 2;
            float4 v = *reinterpret_cast<const float4*>(
                A + (size_t)(bm + r) * lda + k0 + c4);
            As[c4 + 0][r] = v.x; As[c4 + 1][r] = v.y;
            As[c4 + 2][r] = v.z; As[c4 + 3][r] = v.w;
        }
        // W tile: 64x16 = 256 float4, 1 per thread (guard n < N)
        {
            int r = tid >> 2;
            int c4 = (tid & 3) << 2;
            float4 v = make_float4(0.f, 0.f, 0.f, 0.f);
            if (bn + r < N)
                v = *reinterpret_cast<const float4*>(
                    W + (size_t)(bn + r) * ldw + k0 + c4);
            Ws[c4 + 0][r] = v.x; Ws[c4 + 1][r] = v.y;
            Ws[c4 + 2][r] = v.z; Ws[c4 + 3][r] = v.w;
        }
        __syncthreads();
#pragma unroll
        for (int k = 0; k < 16; k++) {
            float4 a0 = *reinterpret_cast<const float4*>(&As[k][ty * 8]);
            float4 a1 = *reinterpret_cast<const float4*>(&As[k][ty * 8 + 4]);
            float4 w0 = *reinterpret_cast<const float4*>(&Ws[k][tx * 4]);
            float a[8] = {a0.x, a0.y, a0.z, a0.w, a1.x, a1.y, a1.z, a1.w};
            float w[4] = {w0.x, w0.y, w0.z, w0.w};
#pragma unroll
            for (int i = 0; i < 8; i++)
#pragma unroll
                for (int j = 0; j < 4; j++) acc[i][j] += a[i] * w[j];
        }
        __syncthreads();
    }

#pragma unroll
    for (int i = 0; i < 8; i++) {
        int m = bm + ty * 8 + i;
        int t = 0;
        if (rowTab) t = tok ? tok[m] : defTok;
#pragma unroll
        for (int j = 0; j < 4; j++) {
            int n = bn + tx * 4 + j;
            if (n < N) {
                float v = acc[i][j];
                if (bias) v += bias[n];
                if (rowTab) v += rowTab[(size_t)t * tabStride + n];
                if (doRelu) v = fmaxf(v, 0.f);
                C[(size_t)m * ldc + n] = v;
            }
        }
    }
}

// ---------------- elementwise / small kernels ----------------
__device__ __forceinline__ float sigmoidf_(float x) {
    return 1.f / (1.f + __expf(-x));
}

// GRU gates. If giTab != null, gi comes from table[tokRow[b]] (encoder path),
// otherwise from the gi buffer (decoder path). Updates h in place.
// If encRow != null, writes h_new of batch row 0 into encRow (enc_pad row t).
__global__ void gru_gates(const float* __restrict__ gi,
                          const float* __restrict__ giTab,
                          const int* __restrict__ tokRow,
                          const float* __restrict__ gh,
                          float* __restrict__ h,
                          float* __restrict__ encRow)
{
    int i = blockIdx.x * blockDim.x + threadIdx.x;
    if (i >= B * H) return;
    int b = i >> 9, j = i & 511;
    float gir, giz, gin;
    if (giTab) {
        int t = tokRow[b];
        const float* p = giTab + (size_t)t * H3;
        gir = p[j]; giz = p[H + j]; gin = p[2 * H + j];
    } else {
        const float* p = gi + (size_t)b * H3;
        gir = p[j]; giz = p[H + j]; gin = p[2 * H + j];
    }
    const float* q = gh + (size_t)b * H3;
    float r = sigmoidf_(gir + q[j]);
    float z = sigmoidf_(giz + q[H + j]);
    float n = tanhf(gin + r * q[2 * H + j]);
    float hv = h[i];
    float hn = (1.f - z) * n + z * hv;
    h[i] = hn;
    if (encRow && b == 0) encRow[j] = hn;
}

// softmax over 41 attention logits per row; writes zero-padded [B,48]
__global__ void softmax_attn(const float* __restrict__ sc,
                             const float* __restrict__ tab,
                             const int* __restrict__ tok, int defTok,
                             float* __restrict__ aw)
{
    int warp = (blockIdx.x * blockDim.x + threadIdx.x) >> 5;
    int lane = threadIdx.x & 31;
    if (warp >= B) return;
    int t = tok ? tok[warp] : defTok;
    float v0 = (lane < L) ? sc[(size_t)warp * L + lane] + tab[(size_t)t * L + lane] : -1e30f;
    float v1 = (lane + 32 < L) ? sc[(size_t)warp * L + lane + 32] + tab[(size_t)t * L + lane + 32] : -1e30f;
    float mx = fmaxf(v0, v1);
#pragma unroll
    for (int o = 16; o > 0; o >>= 1) mx = fmaxf(mx, __shfl_xor_sync(~0u, mx, o));
    float e0 = (lane < L) ? __expf(v0 - mx) : 0.f;
    float e1 = (lane + 32 < L) ? __expf(v1 - mx) : 0.f;
    float s = e0 + e1;
#pragma unroll
    for (int o = 16; o > 0; o >>= 1) s += __shfl_xor_sync(~0u, s, o);
    float inv = 1.f / s;
    aw[(size_t)warp * LP + lane] = (lane < L) ? e0 * inv : 0.f;
    if (lane < 16) aw[(size_t)warp * LP + 32 + lane] = (lane + 32 < L) ? e1 * inv : 0.f;
}

// enc_pad [41,512] -> encpadT [512,48] (zero padded)
__global__ void transpose_encpad()
{
    int i = blockIdx.x * blockDim.x + threadIdx.x;
    if (i >= H * LP) return;
    int j = i / LP, l = i % LP;
    g_encpadT[i] = (l < L) ? g_encpad[l * H + j] : 0.f;
}

// per-row logsumexp over 128 logits + masked gold accumulation
__global__ void out_gold(const float* __restrict__ logits,
                         const int* __restrict__ tgtRow,
                         float* __restrict__ scores)
{
    int warp = (blockIdx.x * blockDim.x + threadIdx.x) >> 5;
    int lane = threadIdx.x & 31;
    if (warp >= B) return;
    const float* row = logits + (size_t)warp * V;
    float v[4];
    float mx = -1e30f;
#pragma unroll
    for (int i = 0; i < 4; i++) { v[i] = row[lane + 32 * i]; mx = fmaxf(mx, v[i]); }
#pragma unroll
    for (int o = 16; o > 0; o >>= 1) mx = fmaxf(mx, __shfl_xor_sync(~0u, mx, o));
    float s = 0.f;
#pragma unroll
    for (int i = 0; i < 4; i++) s += __expf(v[i] - mx);
#pragma unroll
    for (int o = 16; o > 0; o >>= 1) s += __shfl_xor_sync(~0u, s, o);
    if (lane == 0) {
        int tgt = tgtRow[warp];
        if (tgt != 0) {
            float lse = mx + logf(s);
            scores[warp] += row[tgt] - lse;
        }
    }
}

__global__ void init_h(const float* __restrict__ h0)
{
    int i = blockIdx.x * blockDim.x + threadIdx.x;
    if (i < B * H) g_h[i] = h0[i];
    if (i < B) g_scores[i] = 0.f;
}

__global__ void scores_out(float* __restrict__ out)
{
    int i = blockIdx.x * blockDim.x + threadIdx.x;
    if (i < B) out[i] = g_scores[i];
}

// encoder_outputs[b, l, j] = enc_pad[l, j]; grid (82, B), 82*256 == 41*512
__global__ void bcast_out(float* __restrict__ out)
{
    int idx = blockIdx.x * 256 + threadIdx.x;     // 0 .. 20991
    int b = blockIdx.y;
    out[(size_t)B + (size_t)b * (L * H) + idx] = g_encpad[idx];
}

// ---------------- host launch helpers ----------------
static void launch_gemm(float* C, int ldc, const float* A, int lda,
                        const float* W, int ldw, int M, int N, int K,
                        const float* bias,
                        const float* rowTab, int tabStride,
                        const int* tok, int defTok, int relu)
{
    dim3 grid((N + 63) / 64, M / 128);
    gemm_nt<<<grid, 256>>>(M, N, K, A, lda, W, ldw, C, ldc,
                           bias, rowTab, tabStride, tok, defTok, relu);
}

extern "C" void kernel_launch(void* const* d_in, const int* in_sizes, int n_in,
                              void* d_out, int out_size)
{
    const int*   input   = (const int*)  d_in[0];
    const float* enc_h0  = (const float*)d_in[1];
    const int*   target  = (const int*)  d_in[2];
    const float* enc_emb = (const float*)d_in[3];
    const float* enc_Wih = (const float*)d_in[4];
    const float* enc_Whh = (const float*)d_in[5];
    const float* enc_bih = (const float*)d_in[6];
    const float* enc_bhh = (const float*)d_in[7];
    const float* dec_emb = (const float*)d_in[8];
    const float* attn_W  = (const float*)d_in[9];
    const float* attn_b  = (const float*)d_in[10];
    const float* comb_W  = (const float*)d_in[11];
    const float* comb_b  = (const float*)d_in[12];
    const float* dec_Wih = (const float*)d_in[13];
    const float* dec_Whh = (const float*)d_in[14];
    const float* dec_bih = (const float*)d_in[15];
    const float* dec_bhh = (const float*)d_in[16];
    const float* out_W   = (const float*)d_in[17];
    const float* out_b   = (const float*)d_in[18];
    float* out = (float*)d_out;

    float *p_h, *p_gh, *p_gi, *p_attnsc, *p_aw, *p_ctx, *p_x, *p_logits;
    float *p_encpadT, *p_enc_tab, *p_attn_tab, *p_comb_tab, *p_scores, *p_encpad;
    cudaGetSymbolAddress((void**)&p_h, g_h);
    cudaGetSymbolAddress((void**)&p_gh, g_gh);
    cudaGetSymbolAddress((void**)&p_gi, g_gi);
    cudaGetSymbolAddress((void**)&p_attnsc, g_attnsc);
    cudaGetSymbolAddress((void**)&p_aw, g_aw);
    cudaGetSymbolAddress((void**)&p_ctx, g_ctx);
    cudaGetSymbolAddress((void**)&p_x, g_x);
    cudaGetSymbolAddress((void**)&p_logits, g_logits);
    cudaGetSymbolAddress((void**)&p_encpadT, g_encpadT);
    cudaGetSymbolAddress((void**)&p_enc_tab, g_enc_tab);
    cudaGetSymbolAddress((void**)&p_attn_tab, g_attn_tab);
    cudaGetSymbolAddress((void**)&p_comb_tab, g_comb_tab);
    cudaGetSymbolAddress((void**)&p_scores, g_scores);
    cudaGetSymbolAddress((void**)&p_encpad, g_encpad);

    const int EW_GRID = (B * H + 255) / 256;

    // init hidden + scores
    init_h<<<EW_GRID, 256>>>(enc_h0);

    // vocab tables (tiny GEMMs, M = V = 128)
    launch_gemm(p_enc_tab, H3, enc_emb, H, enc_Wih, H, V, H3, H,
                enc_bih, nullptr, 0, nullptr, 0, 0);
    launch_gemm(p_attn_tab, L, dec_emb, H, attn_W, 2 * H, V, L, H,
                attn_b, nullptr, 0, nullptr, 0, 0);
    launch_gemm(p_comb_tab, H, dec_emb, H, comb_W, 2 * H, V, H, H,
                comb_b, nullptr, 0, nullptr, 0, 0);

    // -------- encoder: 41 sequential GRU steps --------
    for (int t = 0; t < L; t++) {
        launch_gemm(p_gh, H3, p_h, H, enc_Whh, H, B, H3, H,
                    enc_bhh, nullptr, 0, nullptr, 0, 0);
        gru_gates<<<EW_GRID, 256>>>(nullptr, p_enc_tab, input + (size_t)t * B,
                                    p_gh, p_h, p_encpad + (size_t)t * H);
    }

    transpose_encpad<<<(H * LP + 255) / 256, 256>>>();

    // -------- decoder: 41 sequential attention+GRU steps --------
    for (int t = 0; t < L; t++) {
        const int* tok = (t == 0) ? nullptr : target + (size_t)(t - 1) * B;
        // gh (depends only on h) and attention scores (depends only on h)
        launch_gemm(p_gh, H3, p_h, H, dec_Whh, H, B, H3, H,
                    dec_bhh, nullptr, 0, nullptr, 0, 0);
        launch_gemm(p_attnsc, L, p_h, H, attn_W + H, 2 * H, B, L, H,
                    nullptr, nullptr, 0, nullptr, 0, 0);
        softmax_attn<<<B / 8, 256>>>(p_attnsc, p_attn_tab, tok, BOS, p_aw);
        // ctx = aw @ enc_pad   (K padded 41 -> 48)
        launch_gemm(p_ctx, H, p_aw, LP, p_encpadT, LP, B, H, LP,
                    nullptr, nullptr, 0, nullptr, 0, 0);
        // x = relu(emb_table[tok] + ctx @ comb_W_ctx.T)   (comb_b folded in table)
        launch_gemm(p_x, H, p_ctx, H, comb_W + H, 2 * H, B, H, H,
                    nullptr, p_comb_tab, H, tok, BOS, 1);
        // gi = x @ Wih.T + bih
        launch_gemm(p_gi, H3, p_x, H, dec_Wih, H, B, H3, H,
                    dec_bih, nullptr, 0, nullptr, 0, 0);
        gru_gates<<<EW_GRID, 256>>>(p_gi, nullptr, nullptr, p_gh, p_h, nullptr);
        // logits = h_new @ out_W.T + out_b ; gold log-prob accumulation
        launch_gemm(p_logits, V, p_h, H, out_W, H, B, V, H,
                    out_b, nullptr, 0, nullptr, 0, 0);
        out_gold<<<B / 8, 256>>>(p_logits, target + (size_t)t * B, p_scores);
    }

    // -------- outputs: [scores (B)] then [encoder_outputs (B, L, H)] --------
    scores_out<<<16, 256>>>(out);
    bcast_out<<<dim3(82, B), 256>>>(out);
}

// round 2
// speedup vs baseline: 1.0012x; 1.0012x over previous
#include <cuda_runtime.h>
#include <math.h>
#include <stdint.h>

#define B 4096
#define H 512
#define H3 1536
#define L 41
#define LP 48
#define V 128
#define BOS 2

// ---------------- device scratch (no allocations allowed) ----------------
__device__ float g_h[B * H];
__device__ float g_gh[B * H3];
__device__ float g_gi[B * H3];
__device__ float g_attnsc[B * L];
__device__ float g_aw[B * LP];
__device__ float g_ctx[B * H];
__device__ float g_x[B * H];
__device__ float g_logits[B * V];
__device__ float g_encpad[L * H];
__device__ float g_encpadT[H * LP];
__device__ float g_enc_tab[V * H3];
__device__ float g_attn_tab[V * L];
__device__ float g_comb_tab[V * H];
__device__ float g_scores[B];

// ---------------- generic NT GEMM: C[m,n] = sum_k A[m,k] * W[n,k] ----------------
// BM=128, BN=64, BK=16, 256 threads, 8x4 per thread.
// Requirements: M % 128 == 0, K % 16 == 0, A/W rows 16B-aligned (lda,ldw % 4 == 0).
__global__ void __launch_bounds__(256) gemm_nt(
    int M, int N, int K,
    const float* __restrict__ A, int lda,
    const float* __restrict__ W, int ldw,
    float* __restrict__ C, int ldc,
    const float* __restrict__ bias,
    const float* __restrict__ rowTab, int tabStride,
    const int* __restrict__ tok, int defTok,
    int doRelu)
{
    __shared__ float As[16][128];
    __shared__ float Ws[16][64];
    const int bm = blockIdx.y * 128;
    const int bn = blockIdx.x * 64;
    const int tid = threadIdx.x;
    const int tx = tid & 15;
    const int ty = tid >> 4;

    float acc[8][4];
#pragma unroll
    for (int i = 0; i < 8; i++)
#pragma unroll
        for (int j = 0; j < 4; j++) acc[i][j] = 0.f;

    for (int k0 = 0; k0 < K; k0 += 16) {
        // A tile: 128x16 = 512 float4, 2 per thread
#pragma unroll
        for (int i = 0; i < 2; i++) {
            int flat = tid + i * 256;
            int r = flat >> 2;
            int c4 = (flat & 3) << 2;
            float4 v = *reinterpret_cast<const float4*>(
                A + (size_t)(bm + r) * lda + k0 + c4);
            As[c4 + 0][r] = v.x; As[c4 + 1][r] = v.y;
            As[c4 + 2][r] = v.z; As[c4 + 3][r] = v.w;
        }
        // W tile: 64x16 = 256 float4, 1 per thread (guard n < N)
        {
            int r = tid >> 2;
            int c4 = (tid & 3) << 2;
            float4 v = make_float4(0.f, 0.f, 0.f, 0.f);
            if (bn + r < N)
                v = *reinterpret_cast<const float4*>(
                    W + (size_t)(bn + r) * ldw + k0 + c4);
            Ws[c4 + 0][r] = v.x; Ws[c4 + 1][r] = v.y;
            Ws[c4 + 2][r] = v.z; Ws[c4 + 3][r] = v.w;
        }
        __syncthreads();
#pragma unroll
        for (int k = 0; k < 16; k++) {
            float4 a0 = *reinterpret_cast<const float4*>(&As[k][ty * 8]);
            float4 a1 = *reinterpret_cast<const float4*>(&As[k][ty * 8 + 4]);
            float4 w0 = *reinterpret_cast<const float4*>(&Ws[k][tx * 4]);
            float a[8] = {a0.x, a0.y, a0.z, a0.w, a1.x, a1.y, a1.z, a1.w};
            float w[4] = {w0.x, w0.y, w0.z, w0.w};
#pragma unroll
            for (int i = 0; i < 8; i++)
#pragma unroll
                for (int j = 0; j < 4; j++) acc[i][j] += a[i] * w[j];
        }
        __syncthreads();
    }

#pragma unroll
    for (int i = 0; i < 8; i++) {
        int m = bm + ty * 8 + i;
        int t = 0;
        if (rowTab) t = tok ? tok[m] : defTok;
#pragma unroll
        for (int j = 0; j < 4; j++) {
            int n = bn + tx * 4 + j;
            if (n < N) {
                float v = acc[i][j];
                if (bias) v += bias[n];
                if (rowTab) v += rowTab[(size_t)t * tabStride + n];
                if (doRelu) v = fmaxf(v, 0.f);
                C[(size_t)m * ldc + n] = v;
            }
        }
    }
}

// ---------------- elementwise / small kernels ----------------
__device__ __forceinline__ float sigmoidf_(float x) {
    return 1.f / (1.f + __expf(-x));
}

// GRU gates. If giTab != null, gi comes from table[tokRow[b]] (encoder path),
// otherwise from the gi buffer (decoder path). Updates h in place.
// If encRow != null, writes h_new of batch row 0 into encRow (enc_pad row t).
__global__ void gru_gates(const float* __restrict__ gi,
                          const float* __restrict__ giTab,
                          const int* __restrict__ tokRow,
                          const float* __restrict__ gh,
                          float* __restrict__ h,
                          float* __restrict__ encRow)
{
    int i = blockIdx.x * blockDim.x + threadIdx.x;
    if (i >= B * H) return;
    int b = i >> 9, j = i & 511;
    float gir, giz, gin;
    if (giTab) {
        int t = tokRow[b];
        const float* p = giTab + (size_t)t * H3;
        gir = p[j]; giz = p[H + j]; gin = p[2 * H + j];
    } else {
        const float* p = gi + (size_t)b * H3;
        gir = p[j]; giz = p[H + j]; gin = p[2 * H + j];
    }
    const float* q = gh + (size_t)b * H3;
    float r = sigmoidf_(gir + q[j]);
    float z = sigmoidf_(giz + q[H + j]);
    float n = tanhf(gin + r * q[2 * H + j]);
    float hv = h[i];
    float hn = (1.f - z) * n + z * hv;
    h[i] = hn;
    if (encRow && b == 0) encRow[j] = hn;
}

// softmax over 41 attention logits per row; writes zero-padded [B,48]
__global__ void softmax_attn(const float* __restrict__ sc,
                             const float* __restrict__ tab,
                             const int* __restrict__ tok, int defTok,
                             float* __restrict__ aw)
{
    int warp = (blockIdx.x * blockDim.x + threadIdx.x) >> 5;
    int lane = threadIdx.x & 31;
    if (warp >= B) return;
    int t = tok ? tok[warp] : defTok;
    float v0 = (lane < L) ? sc[(size_t)warp * L + lane] + tab[(size_t)t * L + lane] : -1e30f;
    float v1 = (lane + 32 < L) ? sc[(size_t)warp * L + lane + 32] + tab[(size_t)t * L + lane + 32] : -1e30f;
    float mx = fmaxf(v0, v1);
#pragma unroll
    for (int o = 16; o > 0; o >>= 1) mx = fmaxf(mx, __shfl_xor_sync(~0u, mx, o));
    float e0 = (lane < L) ? __expf(v0 - mx) : 0.f;
    float e1 = (lane + 32 < L) ? __expf(v1 - mx) : 0.f;
    float s = e0 + e1;
#pragma unroll
    for (int o = 16; o > 0; o >>= 1) s += __shfl_xor_sync(~0u, s, o);
    float inv = 1.f / s;
    aw[(size_t)warp * LP + lane] = (lane < L) ? e0 * inv : 0.f;
    if (lane < 16) aw[(size_t)warp * LP + 32 + lane] = (lane + 32 < L) ? e1 * inv : 0.f;
}

// enc_pad [41,512] -> encpadT [512,48] (zero padded)
__global__ void transpose_encpad()
{
    int i = blockIdx.x * blockDim.x + threadIdx.x;
    if (i >= H * LP) return;
    int j = i / LP, l = i % LP;
    g_encpadT[i] = (l < L) ? g_encpad[l * H + j] : 0.f;
}

// per-row logsumexp over 128 logits + masked gold accumulation
__global__ void out_gold(const float* __restrict__ logits,
                         const int* __restrict__ tgtRow,
                         float* __restrict__ scores)
{
    int warp = (blockIdx.x * blockDim.x + threadIdx.x) >> 5;
    int lane = threadIdx.x & 31;
    if (warp >= B) return;
    const float* row = logits + (size_t)warp * V;
    float v[4];
    float mx = -1e30f;
#pragma unroll
    for (int i = 0; i < 4; i++) { v[i] = row[lane + 32 * i]; mx = fmaxf(mx, v[i]); }
#pragma unroll
    for (int o = 16; o > 0; o >>= 1) mx = fmaxf(mx, __shfl_xor_sync(~0u, mx, o));
    float s = 0.f;
#pragma unroll
    for (int i = 0; i < 4; i++) s += __expf(v[i] - mx);
#pragma unroll
    for (int o = 16; o > 0; o >>= 1) s += __shfl_xor_sync(~0u, s, o);
    if (lane == 0) {
        int tgt = tgtRow[warp];
        if (tgt != 0) {
            float lse = mx + logf(s);
            scores[warp] += row[tgt] - lse;
        }
    }
}

__global__ void init_h(const float* __restrict__ h0)
{
    int i = blockIdx.x * blockDim.x + threadIdx.x;
    if (i < B * H) g_h[i] = h0[i];
    if (i < B) g_scores[i] = 0.f;
}

__global__ void scores_out(float* __restrict__ out)
{
    int i = blockIdx.x * blockDim.x + threadIdx.x;
    if (i < B) out[i] = g_scores[i];
}

// encoder_outputs[b, l, j] = enc_pad[l, j]; grid (82, B), 82*256 == 41*512
__global__ void bcast_out(float* __restrict__ out)
{
    int idx = blockIdx.x * 256 + threadIdx.x;     // 0 .. 20991
    int b = blockIdx.y;
    out[(size_t)B + (size_t)b * (L * H) + idx] = g_encpad[idx];
}

// ---------------- host launch helpers ----------------
static void launch_gemm(float* C, int ldc, const float* A, int lda,
                        const float* W, int ldw, int M, int N, int K,
                        const float* bias,
                        const float* rowTab, int tabStride,
                        const int* tok, int defTok, int relu)
{
    dim3 grid((N + 63) / 64, M / 128);
    gemm_nt<<<grid, 256>>>(M, N, K, A, lda, W, ldw, C, ldc,
                           bias, rowTab, tabStride, tok, defTok, relu);
}

extern "C" void kernel_launch(void* const* d_in, const int* in_sizes, int n_in,
                              void* d_out, int out_size)
{
    const int*   input   = (const int*)  d_in[0];
    const float* enc_h0  = (const float*)d_in[1];
    const int*   target  = (const int*)  d_in[2];
    const float* enc_emb = (const float*)d_in[3];
    const float* enc_Wih = (const float*)d_in[4];
    const float* enc_Whh = (const float*)d_in[5];
    const float* enc_bih = (const float*)d_in[6];
    const float* enc_bhh = (const float*)d_in[7];
    const float* dec_emb = (const float*)d_in[8];
    const float* attn_W  = (const float*)d_in[9];
    const float* attn_b  = (const float*)d_in[10];
    const float* comb_W  = (const float*)d_in[11];
    const float* comb_b  = (const float*)d_in[12];
    const float* dec_Wih = (const float*)d_in[13];
    const float* dec_Whh = (const float*)d_in[14];
    const float* dec_bih = (const float*)d_in[15];
    const float* dec_bhh = (const float*)d_in[16];
    const float* out_W   = (const float*)d_in[17];
    const float* out_b   = (const float*)d_in[18];
    float* out = (float*)d_out;

    float *p_h, *p_gh, *p_gi, *p_attnsc, *p_aw, *p_ctx, *p_x, *p_logits;
    float *p_encpadT, *p_enc_tab, *p_attn_tab, *p_comb_tab, *p_scores, *p_encpad;
    cudaGetSymbolAddress((void**)&p_h, g_h);
    cudaGetSymbolAddress((void**)&p_gh, g_gh);
    cudaGetSymbolAddress((void**)&p_gi, g_gi);
    cudaGetSymbolAddress((void**)&p_attnsc, g_attnsc);
    cudaGetSymbolAddress((void**)&p_aw, g_aw);
    cudaGetSymbolAddress((void**)&p_ctx, g_ctx);
    cudaGetSymbolAddress((void**)&p_x, g_x);
    cudaGetSymbolAddress((void**)&p_logits, g_logits);
    cudaGetSymbolAddress((void**)&p_encpadT, g_encpadT);
    cudaGetSymbolAddress((void**)&p_enc_tab, g_enc_tab);
    cudaGetSymbolAddress((void**)&p_attn_tab, g_attn_tab);
    cudaGetSymbolAddress((void**)&p_comb_tab, g_comb_tab);
    cudaGetSymbolAddress((void**)&p_scores, g_scores);
    cudaGetSymbolAddress((void**)&p_encpad, g_encpad);

    const int EW_GRID = (B * H + 255) / 256;

    // init hidden + scores
    init_h<<<EW_GRID, 256>>>(enc_h0);

    // vocab tables (tiny GEMMs, M = V = 128)
    launch_gemm(p_enc_tab, H3, enc_emb, H, enc_Wih, H, V, H3, H,
                enc_bih, nullptr, 0, nullptr, 0, 0);
    launch_gemm(p_attn_tab, L, dec_emb, H, attn_W, 2 * H, V, L, H,
                attn_b, nullptr, 0, nullptr, 0, 0);
    launch_gemm(p_comb_tab, H, dec_emb, H, comb_W, 2 * H, V, H, H,
                comb_b, nullptr, 0, nullptr, 0, 0);

    // -------- encoder: 41 sequential GRU steps --------
    for (int t = 0; t < L; t++) {
        launch_gemm(p_gh, H3, p_h, H, enc_Whh, H, B, H3, H,
                    enc_bhh, nullptr, 0, nullptr, 0, 0);
        gru_gates<<<EW_GRID, 256>>>(nullptr, p_enc_tab, input + (size_t)t * B,
                                    p_gh, p_h, p_encpad + (size_t)t * H);
    }

    transpose_encpad<<<(H * LP + 255) / 256, 256>>>();

    // -------- decoder: 41 sequential attention+GRU steps --------
    for (int t = 0; t < L; t++) {
        const int* tok = (t == 0) ? nullptr : target + (size_t)(t - 1) * B;
        // gh (depends only on h) and attention scores (depends only on h)
        launch_gemm(p_gh, H3, p_h, H, dec_Whh, H, B, H3, H,
                    dec_bhh, nullptr, 0, nullptr, 0, 0);
        launch_gemm(p_attnsc, L, p_h, H, attn_W + H, 2 * H, B, L, H,
                    nullptr, nullptr, 0, nullptr, 0, 0);
        softmax_attn<<<B / 8, 256>>>(p_attnsc, p_attn_tab, tok, BOS, p_aw);
        // ctx = aw @ enc_pad   (K padded 41 -> 48)
        launch_gemm(p_ctx, H, p_aw, LP, p_encpadT, LP, B, H, LP,
                    nullptr, nullptr, 0, nullptr, 0, 0);
        // x = relu(emb_table[tok] + ctx @ comb_W_ctx.T)   (comb_b folded in table)
        launch_gemm(p_x, H, p_ctx, H, comb_W + H, 2 * H, B, H, H,
                    nullptr, p_comb_tab, H, tok, BOS, 1);
        // gi = x @ Wih.T + bih
        launch_gemm(p_gi, H3, p_x, H, dec_Wih, H, B, H3, H,
                    dec_bih, nullptr, 0, nullptr, 0, 0);
        gru_gates<<<EW_GRID, 256>>>(p_gi, nullptr, nullptr, p_gh, p_h, nullptr);
        // logits = h_new @ out_W.T + out_b ; gold log-prob accumulation
        launch_gemm(p_logits, V, p_h, H, out_W, H, B, V, H,
                    out_b, nullptr, 0, nullptr, 0, 0);
        out_gold<<<B / 8, 256>>>(p_logits, target + (size_t)t * B, p_scores);
    }

    // -------- outputs: [scores (B)] then [encoder_outputs (B, L, H)] --------
    scores_out<<<16, 256>>>(out);
    bcast_out<<<dim3(82, B), 256>>>(out);
}

// round 4
// speedup vs baseline: 2.2591x; 2.2564x over previous
#include <cuda_runtime.h>
#include <cuda_bf16.h>
#include <math.h>
#include <stdint.h>

#define B 4096
#define H 512
#define H3 1536
#define L 41
#define LP 48
#define V 128
#define BOS 2
#define TCK 1536          /* split K: [hi | lo | hi] */
#define BKC 64            /* K chunk (bf16 elems) */
#define NCHUNK 24         /* TCK / BKC */
#define NCOMBO 1705       /* 1536 gh + 41 attn + 128 logits */

// ====================== device scratch ======================
__device__ __align__(128) float g_h[B * H];
__device__ __align__(128) float g_gh[B * H3];
__device__ __align__(128) float g_gi[B * H3];
__device__ __align__(128) float g_attnsc[B * L];
__device__ __align__(128) float g_aw[B * LP];
__device__ __align__(128) float g_logits[B * V];
__device__ __align__(128) float g_encpad[L * H];
__device__ __align__(128) float g_encpadT[H * LP];
__device__ __align__(128) float g_enc_tab[V * H3];
__device__ __align__(128) float g_attn_tab[V * L];
__device__ __align__(128) float g_comb_tab[V * H];
__device__ __align__(128) float g_scores[B];
__device__ __align__(128) float g_combo_bias[1792];

__device__ __align__(128) __nv_bfloat16 g_hsplit[B * TCK];
__device__ __align__(128) __nv_bfloat16 g_xsplit[B * TCK];
__device__ __align__(128) __nv_bfloat16 g_ctxsplit[B * TCK];
__device__ __align__(128) __nv_bfloat16 g_w_enc[H3 * TCK];
__device__ __align__(128) __nv_bfloat16 g_w_gi[H3 * TCK];
__device__ __align__(128) __nv_bfloat16 g_w_x[H * TCK];
__device__ __align__(128) __nv_bfloat16 g_w_combo[1792 * TCK];

// ====================== asm helpers (non-'a'-gated only) ======================
__device__ __forceinline__ uint32_t smem_u32(const void* p) {
    uint32_t a;
    asm("{ .reg .u64 t; cvta.to.shared.u64 t, %1; cvt.u32.u64 %0, t; }" : "=r"(a) : "l"(p));
    return a;
}
__device__ __forceinline__ void cp16(uint32_t s, const void* g) {
    asm volatile("cp.async.cg.shared.global [%0], [%1], 16;" :: "r"(s), "l"(g));
}
#define CP_COMMIT() asm volatile("cp.async.commit_group;" ::: "memory")
#define CP_WAIT1()  asm volatile("cp.async.wait_group 1;" ::: "memory")
#define CP_WAIT0()  asm volatile("cp.async.wait_group 0;" ::: "memory")
#define LDMX4(r0, r1, r2, r3, a) \
    asm volatile("ldmatrix.sync.aligned.m8n8.x4.shared.b16 {%0,%1,%2,%3}, [%4];" \
        : "=r"(r0), "=r"(r1), "=r"(r2), "=r"(r3) : "r"(a))
#define MMA16816(d, a, bb) \
    asm volatile("mma.sync.aligned.m16n8k16.row.col.f32.bf16.bf16.f32 " \
        "{%0,%1,%2,%3}, {%4,%5,%6,%7}, {%8,%9}, {%0,%1,%2,%3};" \
        : "+f"((d)[0]), "+f"((d)[1]), "+f"((d)[2]), "+f"((d)[3]) \
        : "r"((a)[0]), "r"((a)[1]), "r"((a)[2]), "r"((a)[3]), \
          "r"((bb)[0]), "r"((bb)[1]))

// ====================== HMMA GEMM ======================
// C[4096, N] = A[4096, TCK]bf16 * W[N, TCK]bf16^T   (fp32 accum)
// BM=128, BN=128, BK=64, 256 threads (8 warps: 2m x 4n, warp tile 64x32).
// smem: padded pitch 144B per 64-elem (128B) row; double buffered.
// mode 0: C0[m*N+n] = acc (+bias)
// mode 1: combo: n<1536 -> C0(ld 1536,+bias); 1536..1576 -> C1(ld 41,+bias); else C2(ld 128,+bias)
// mode 2: v = relu(acc + tab[tok[m]*512+n]); split-write -> splitDst[m*TCK + {n, n+512, n+1024}]
#define PITCH 144
#define TILEB (128 * PITCH)          /* 18432 */
#define SMEM_MMA (4 * TILEB)         /* 73728: A0 B0 A1 B1 */

struct EpiArgs {
    int mode; int N;
    float* C0; float* C1; float* C2;
    const float* bias; const float* tab;
    __nv_bfloat16* splitDst;
};

__device__ __forceinline__ void store_elem(const EpiArgs& e, size_t m, int n,
                                           float v, int tk)
{
    if (n >= e.N) return;
    if (e.mode == 0) {
        if (e.bias) v += e.bias[n];
        e.C0[m * e.N + n] = v;
    } else if (e.mode == 1) {
        v += e.bias[n];
        if (n < 1536)      e.C0[m * 1536 + n] = v;
        else if (n < 1577) e.C1[m * 41 + (n - 1536)] = v;
        else               e.C2[m * 128 + (n - 1577)] = v;
    } else {
        v += e.tab[(size_t)tk * 512 + n];
        v = fmaxf(v, 0.f);
        __nv_bfloat16 hi = __float2bfloat16(v);
        __nv_bfloat16 lo = __float2bfloat16(v - __bfloat162float(hi));
        e.splitDst[m * TCK + n] = hi;
        e.splitDst[m * TCK + 512 + n] = lo;
        e.splitDst[m * TCK + 1024 + n] = hi;
    }
}

__global__ void __launch_bounds__(256) gemm_mma(
    int N,
    const __nv_bfloat16* __restrict__ A,
    const __nv_bfloat16* __restrict__ W,
    int mode,
    float* __restrict__ C0, float* __restrict__ C1, float* __restrict__ C2,
    const float* __restrict__ bias,
    const float* __restrict__ tab,
    const int* __restrict__ tok, int defTok,
    __nv_bfloat16* __restrict__ splitDst)
{
    extern __shared__ __align__(128) char smem[];
    const uint32_t sb = smem_u32(smem);
    const int tid = threadIdx.x;
    const int lane = tid & 31;
    const int wid = tid >> 5;
    const int wm = wid >> 2;          // 0..1
    const int wn = wid & 3;           // 0..3
    const int bm = blockIdx.y * 128;
    const int bn = blockIdx.x * 128;

    // ---- async tile loader: chunk c -> buffer (c&1) ----
    auto load_tile = [&](int c) {
        const int buf = c & 1;
        const uint32_t sA = sb + buf * 2 * TILEB;
        const uint32_t sB = sA + TILEB;
        const size_t koff = (size_t)c * BKC;
#pragma unroll
        for (int i = 0; i < 4; i++) {
            int ch = tid + i * 256;           // 0..1023
            int row = ch >> 3;
            int col = ch & 7;                 // 16B units within 128B row
            cp16(sA + row * PITCH + col * 16,
                 (const char*)(A + (size_t)(bm + row) * TCK + koff) + col * 16);
            int rowB = bn + row; if (rowB >= N) rowB = N - 1;
            cp16(sB + row * PITCH + col * 16,
                 (const char*)(W + (size_t)rowB * TCK + koff) + col * 16);
        }
        CP_COMMIT();
    };

    float acc[4][4][4];
#pragma unroll
    for (int i = 0; i < 4; i++)
#pragma unroll
        for (int j = 0; j < 4; j++)
#pragma unroll
            for (int k = 0; k < 4; k++) acc[i][j][k] = 0.f;

    const uint32_t rowsel = lane & 15;
    const uint32_t khalf = (uint32_t)(lane >> 4);   // 0/1 -> +16B

    load_tile(0);
    for (int c = 0; c < NCHUNK; c++) {
        if (c + 1 < NCHUNK) { load_tile(c + 1); CP_WAIT1(); }
        else                { CP_WAIT0(); }
        __syncthreads();

        const uint32_t sA = sb + (c & 1) * 2 * TILEB + (wm * 64) * PITCH;
        const uint32_t sB = sb + (c & 1) * 2 * TILEB + TILEB + (wn * 32) * PITCH;
#pragma unroll
        for (int k16 = 0; k16 < 4; k16++) {
            const uint32_t kb = k16 * 32 + khalf * 16;
            uint32_t a[4][4];
#pragma unroll
            for (int mi = 0; mi < 4; mi++)
                LDMX4(a[mi][0], a[mi][1], a[mi][2], a[mi][3],
                      sA + (mi * 16 + rowsel) * PITCH + kb);
            uint32_t bf[4][2];
#pragma unroll
            for (int np = 0; np < 2; np++) {
                uint32_t r0, r1, r2, r3;
                LDMX4(r0, r1, r2, r3, sB + (np * 16 + rowsel) * PITCH + kb);
                bf[np * 2][0] = r0; bf[np * 2 + 1][0] = r1;
                bf[np * 2][1] = r2; bf[np * 2 + 1][1] = r3;
            }
#pragma unroll
            for (int mi = 0; mi < 4; mi++)
#pragma unroll
                for (int ni = 0; ni < 4; ni++)
                    MMA16816(acc[mi][ni], a[mi], bf[ni]);
        }
        __syncthreads();
    }

    // ---- epilogue ----
    EpiArgs e{mode, N, C0, C1, C2, bias, tab, splitDst};
    const int qr = lane >> 2;
    const int qc = (lane & 3) * 2;
#pragma unroll
    for (int mi = 0; mi < 4; mi++) {
        const size_t m0 = (size_t)(bm + wm * 64 + mi * 16 + qr);
        const size_t m1 = m0 + 8;
        int tk0 = 0, tk1 = 0;
        if (mode == 2) {
            tk0 = tok ? tok[m0] : defTok;
            tk1 = tok ? tok[m1] : defTok;
        }
#pragma unroll
        for (int ni = 0; ni < 4; ni++) {
            const int n0 = bn + wn * 32 + ni * 8 + qc;
            float* a4 = acc[mi][ni];
            store_elem(e, m0, n0,     a4[0], tk0);
            store_elem(e, m0, n0 + 1, a4[1], tk0);
            store_elem(e, m1, n0,     a4[2], tk1);
            store_elem(e, m1, n0 + 1, a4[3], tk1);
        }
    }
}

// ====================== fp32 SIMT GEMM (prep / ctx) ======================
__global__ void __launch_bounds__(256) gemm_nt(
    int M, int N, int K,
    const float* __restrict__ A, int lda,
    const float* __restrict__ W, int ldw,
    float* __restrict__ C, int ldc,
    const float* __restrict__ bias,
    __nv_bfloat16* __restrict__ splitDst)
{
    __shared__ float As[16][128];
    __shared__ float Ws[16][64];
    const int bm = blockIdx.y * 128;
    const int bn = blockIdx.x * 64;
    const int tid = threadIdx.x;
    const int tx = tid & 15;
    const int ty = tid >> 4;

    float acc[8][4];
#pragma unroll
    for (int i = 0; i < 8; i++)
#pragma unroll
        for (int j = 0; j < 4; j++) acc[i][j] = 0.f;

    for (int k0 = 0; k0 < K; k0 += 16) {
#pragma unroll
        for (int i = 0; i < 2; i++) {
            int flat = tid + i * 256;
            int r = flat >> 2;
            int c4 = (flat & 3) << 2;
            float4 v = *reinterpret_cast<const float4*>(A + (size_t)(bm + r) * lda + k0 + c4);
            As[c4 + 0][r] = v.x; As[c4 + 1][r] = v.y;
            As[c4 + 2][r] = v.z; As[c4 + 3][r] = v.w;
        }
        {
            int r = tid >> 2;
            int c4 = (tid & 3) << 2;
            float4 v = make_float4(0.f, 0.f, 0.f, 0.f);
            if (bn + r < N)
                v = *reinterpret_cast<const float4*>(W + (size_t)(bn + r) * ldw + k0 + c4);
            Ws[c4 + 0][r] = v.x; Ws[c4 + 1][r] = v.y;
            Ws[c4 + 2][r] = v.z; Ws[c4 + 3][r] = v.w;
        }
        __syncthreads();
#pragma unroll
        for (int k = 0; k < 16; k++) {
            float4 a0 = *reinterpret_cast<const float4*>(&As[k][ty * 8]);
            float4 a1 = *reinterpret_cast<const float4*>(&As[k][ty * 8 + 4]);
            float4 w0 = *reinterpret_cast<const float4*>(&Ws[k][tx * 4]);
            float a[8] = {a0.x, a0.y, a0.z, a0.w, a1.x, a1.y, a1.z, a1.w};
            float w[4] = {w0.x, w0.y, w0.z, w0.w};
#pragma unroll
            for (int i = 0; i < 8; i++)
#pragma unroll
                for (int j = 0; j < 4; j++) acc[i][j] += a[i] * w[j];
        }
        __syncthreads();
    }

#pragma unroll
    for (int i = 0; i < 8; i++) {
        size_t mrow = (size_t)(bm + ty * 8 + i);
#pragma unroll
        for (int j = 0; j < 4; j++) {
            int n = bn + tx * 4 + j;
            if (n < N) {
                float v = acc[i][j];
                if (bias) v += bias[n];
                if (splitDst) {
                    __nv_bfloat16 hi = __float2bfloat16(v);
                    __nv_bfloat16 lo = __float2bfloat16(v - __bfloat162float(hi));
                    splitDst[mrow * TCK + n] = hi;
                    splitDst[mrow * TCK + 512 + n] = lo;
                    splitDst[mrow * TCK + 1024 + n] = hi;
                } else {
                    C[mrow * ldc + n] = v;
                }
            }
        }
    }
}

// ====================== elementwise / small kernels ======================
__device__ __forceinline__ float sigmoidf_(float x) { return 1.f / (1.f + __expf(-x)); }

__global__ void gru_gates(const float* __restrict__ gi,
                          const float* __restrict__ giTab,
                          const int* __restrict__ tokRow,
                          const float* __restrict__ gh,
                          float* __restrict__ h,
                          __nv_bfloat16* __restrict__ hsplit,
                          float* __restrict__ encRow)
{
    int i = blockIdx.x * blockDim.x + threadIdx.x;
    if (i >= B * H) return;
    int b = i >> 9, j = i & 511;
    float gir, giz, gin;
    if (giTab) {
        int t = tokRow[b];
        const float* p = giTab + (size_t)t * H3;
        gir = p[j]; giz = p[H + j]; gin = p[2 * H + j];
    } else {
        const float* p = gi + (size_t)b * H3;
        gir = p[j]; giz = p[H + j]; gin = p[2 * H + j];
    }
    const float* q = gh + (size_t)b * H3;
    float r = sigmoidf_(gir + q[j]);
    float z = sigmoidf_(giz + q[H + j]);
    float n = tanhf(gin + r * q[2 * H + j]);
    float hv = h[i];
    float hn = (1.f - z) * n + z * hv;
    h[i] = hn;
    __nv_bfloat16 hi = __float2bfloat16(hn);
    __nv_bfloat16 lo = __float2bfloat16(hn - __bfloat162float(hi));
    size_t base = (size_t)b * TCK + j;
    hsplit[base] = hi; hsplit[base + 512] = lo; hsplit[base + 1024] = hi;
    if (encRow && b == 0) encRow[j] = hn;
}

__global__ void softmax_attn(const float* __restrict__ sc,
                             const float* __restrict__ tab,
                             const int* __restrict__ tok, int defTok,
                             float* __restrict__ aw)
{
    int warp = (blockIdx.x * blockDim.x + threadIdx.x) >> 5;
    int lane = threadIdx.x & 31;
    if (warp >= B) return;
    int t = tok ? tok[warp] : defTok;
    float v0 = (lane < L) ? sc[(size_t)warp * L + lane] + tab[(size_t)t * L + lane] : -1e30f;
    float v1 = (lane + 32 < L) ? sc[(size_t)warp * L + lane + 32] + tab[(size_t)t * L + lane + 32] : -1e30f;
    float mx = fmaxf(v0, v1);
#pragma unroll
    for (int o = 16; o > 0; o >>= 1) mx = fmaxf(mx, __shfl_xor_sync(~0u, mx, o));
    float e0 = (lane < L) ? __expf(v0 - mx) : 0.f;
    float e1 = (lane + 32 < L) ? __expf(v1 - mx) : 0.f;
    float s = e0 + e1;
#pragma unroll
    for (int o = 16; o > 0; o >>= 1) s += __shfl_xor_sync(~0u, s, o);
    float inv = 1.f / s;
    aw[(size_t)warp * LP + lane] = (lane < L) ? e0 * inv : 0.f;
    if (lane < 16) aw[(size_t)warp * LP + 32 + lane] = (lane + 32 < L) ? e1 * inv : 0.f;
}

__global__ void transpose_encpad()
{
    int i = blockIdx.x * blockDim.x + threadIdx.x;
    if (i >= H * LP) return;
    int j = i / LP, l = i % LP;
    g_encpadT[i] = (l < L) ? g_encpad[l * H + j] : 0.f;
}

__global__ void out_gold(const float* __restrict__ logits,
                         const int* __restrict__ tgtRow,
                         float* __restrict__ scores)
{
    int warp = (blockIdx.x * blockDim.x + threadIdx.x) >> 5;
    int lane = threadIdx.x & 31;
    if (warp >= B) return;
    const float* row = logits + (size_t)warp * V;
    float v[4];
    float mx = -1e30f;
#pragma unroll
    for (int i = 0; i < 4; i++) { v[i] = row[lane + 32 * i]; mx = fmaxf(mx, v[i]); }
#pragma unroll
    for (int o = 16; o > 0; o >>= 1) mx = fmaxf(mx, __shfl_xor_sync(~0u, mx, o));
    float s = 0.f;
#pragma unroll
    for (int i = 0; i < 4; i++) s += __expf(v[i] - mx);
#pragma unroll
    for (int o = 16; o > 0; o >>= 1) s += __shfl_xor_sync(~0u, s, o);
    if (lane == 0) {
        int tgt = tgtRow[warp];
        if (tgt != 0) scores[warp] += row[tgt] - (mx + logf(s));
    }
}

__global__ void init_h(const float* __restrict__ h0)
{
    int i = blockIdx.x * blockDim.x + threadIdx.x;
    if (i >= B * H) return;
    float v = h0[i];
    g_h[i] = v;
    int b = i >> 9, j = i & 511;
    __nv_bfloat16 hi = __float2bfloat16(v);
    __nv_bfloat16 lo = __float2bfloat16(v - __bfloat162float(hi));
    size_t base = (size_t)b * TCK + j;
    g_hsplit[base] = hi; g_hsplit[base + 512] = lo; g_hsplit[base + 1024] = hi;
    if (i < B) g_scores[i] = 0.f;
}

// split fp32 weights -> [Wh | Wh | Wl]
__global__ void split_w(__nv_bfloat16* __restrict__ dst,
                        const float* __restrict__ src, int ldw, int colOff,
                        int rows, int dstRowOff)
{
    int i = blockIdx.x * blockDim.x + threadIdx.x;
    if (i >= rows * 512) return;
    int r = i >> 9, k = i & 511;
    float w = src[(size_t)r * ldw + colOff + k];
    __nv_bfloat16 hi = __float2bfloat16(w);
    __nv_bfloat16 lo = __float2bfloat16(w - __bfloat162float(hi));
    size_t base = (size_t)(dstRowOff + r) * TCK + k;
    dst[base] = hi; dst[base + 512] = hi; dst[base + 1024] = lo;
}

__global__ void build_combo_bias(const float* __restrict__ bhh,
                                 const float* __restrict__ outb)
{
    int n = blockIdx.x * blockDim.x + threadIdx.x;
    if (n >= NCOMBO) return;
    g_combo_bias[n] = (n < 1536) ? bhh[n] : ((n < 1577) ? 0.f : outb[n - 1577]);
}

__global__ void scores_out(float* __restrict__ out)
{
    int i = blockIdx.x * blockDim.x + threadIdx.x;
    if (i < B) out[i] = g_scores[i];
}

__global__ void bcast_out(float* __restrict__ out)
{
    int idx = blockIdx.x * 256 + threadIdx.x;
    int b = blockIdx.y;
    out[(size_t)B + (size_t)b * (L * H) + idx] = g_encpad[idx];
}

// ====================== host ======================
static void launch_nt(float* C, int ldc, const float* A, int lda,
                      const float* W, int ldw, int M, int N, int K,
                      const float* bias, __nv_bfloat16* splitDst)
{
    dim3 grid((N + 63) / 64, M / 128);
    gemm_nt<<<grid, 256>>>(M, N, K, A, lda, W, ldw, C, ldc, bias, splitDst);
}

static void launch_tc(int N, const __nv_bfloat16* A, const __nv_bfloat16* W,
                      int mode, float* C0, float* C1, float* C2,
                      const float* bias, const float* tab,
                      const int* tok, int defTok, __nv_bfloat16* splitDst)
{
    dim3 grid((N + 127) / 128, B / 128);
    gemm_mma<<<grid, 256, SMEM_MMA>>>(N, A, W, mode, C0, C1, C2, bias,
                                      tab, tok, defTok, splitDst);
}

extern "C" void kernel_launch(void* const* d_in, const int* in_sizes, int n_in,
                              void* d_out, int out_size)
{
    const int*   input   = (const int*)  d_in[0];
    const float* enc_h0  = (const float*)d_in[1];
    const int*   target  = (const int*)  d_in[2];
    const float* enc_emb = (const float*)d_in[3];
    const float* enc_Wih = (const float*)d_in[4];
    const float* enc_Whh = (const float*)d_in[5];
    const float* enc_bih = (const float*)d_in[6];
    const float* enc_bhh = (const float*)d_in[7];
    const float* dec_emb = (const float*)d_in[8];
    const float* attn_W  = (const float*)d_in[9];
    const float* attn_b  = (const float*)d_in[10];
    const float* comb_W  = (const float*)d_in[11];
    const float* comb_b  = (const float*)d_in[12];
    const float* dec_Wih = (const float*)d_in[13];
    const float* dec_Whh = (const float*)d_in[14];
    const float* dec_bih = (const float*)d_in[15];
    const float* dec_bhh = (const float*)d_in[16];
    const float* out_W   = (const float*)d_in[17];
    const float* out_b   = (const float*)d_in[18];
    float* out = (float*)d_out;

    cudaFuncSetAttribute(gemm_mma, cudaFuncAttributeMaxDynamicSharedMemorySize, SMEM_MMA);

    float *p_h, *p_gh, *p_gi, *p_attnsc, *p_aw, *p_logits, *p_encpad, *p_encpadT;
    float *p_enc_tab, *p_attn_tab, *p_comb_tab, *p_scores, *p_cbias;
    __nv_bfloat16 *p_hsplit, *p_xsplit, *p_ctxsplit, *p_wenc, *p_wgi, *p_wx, *p_wcombo;
    cudaGetSymbolAddress((void**)&p_h, g_h);
    cudaGetSymbolAddress((void**)&p_gh, g_gh);
    cudaGetSymbolAddress((void**)&p_gi, g_gi);
    cudaGetSymbolAddress((void**)&p_attnsc, g_attnsc);
    cudaGetSymbolAddress((void**)&p_aw, g_aw);
    cudaGetSymbolAddress((void**)&p_logits, g_logits);
    cudaGetSymbolAddress((void**)&p_encpad, g_encpad);
    cudaGetSymbolAddress((void**)&p_encpadT, g_encpadT);
    cudaGetSymbolAddress((void**)&p_enc_tab, g_enc_tab);
    cudaGetSymbolAddress((void**)&p_attn_tab, g_attn_tab);
    cudaGetSymbolAddress((void**)&p_comb_tab, g_comb_tab);
    cudaGetSymbolAddress((void**)&p_scores, g_scores);
    cudaGetSymbolAddress((void**)&p_cbias, g_combo_bias);
    cudaGetSymbolAddress((void**)&p_hsplit, g_hsplit);
    cudaGetSymbolAddress((void**)&p_xsplit, g_xsplit);
    cudaGetSymbolAddress((void**)&p_ctxsplit, g_ctxsplit);
    cudaGetSymbolAddress((void**)&p_wenc, g_w_enc);
    cudaGetSymbolAddress((void**)&p_wgi, g_w_gi);
    cudaGetSymbolAddress((void**)&p_wx, g_w_x);
    cudaGetSymbolAddress((void**)&p_wcombo, g_w_combo);

    const int EW = (B * H + 255) / 256;

    // ---- prep ----
    init_h<<<EW, 256>>>(enc_h0);
    launch_nt(p_enc_tab, H3, enc_emb, H, enc_Wih, H, V, H3, H, enc_bih, nullptr);
    launch_nt(p_attn_tab, L, dec_emb, H, attn_W, 2 * H, V, L, H, attn_b, nullptr);
    launch_nt(p_comb_tab, H, dec_emb, H, comb_W, 2 * H, V, H, H, comb_b, nullptr);
    split_w<<<(H3 * 512 + 255) / 256, 256>>>(p_wenc, enc_Whh, H, 0, H3, 0);
    split_w<<<(H3 * 512 + 255) / 256, 256>>>(p_wgi, dec_Wih, H, 0, H3, 0);
    split_w<<<(H * 512 + 255) / 256, 256>>>(p_wx, comb_W, 2 * H, H, H, 0);
    split_w<<<(H3 * 512 + 255) / 256, 256>>>(p_wcombo, dec_Whh, H, 0, H3, 0);
    split_w<<<(L * 512 + 255) / 256, 256>>>(p_wcombo, attn_W, 2 * H, H, L, 1536);
    split_w<<<(V * 512 + 255) / 256, 256>>>(p_wcombo, out_W, H, 0, V, 1577);
    build_combo_bias<<<(NCOMBO + 255) / 256, 256>>>(dec_bhh, out_b);

    // ---- encoder: 41 sequential GRU steps ----
    for (int t = 0; t < L; t++) {
        launch_tc(H3, p_hsplit, p_wenc, 0, p_gh, nullptr, nullptr,
                  enc_bhh, nullptr, nullptr, 0, nullptr);
        gru_gates<<<EW, 256>>>(nullptr, p_enc_tab, input + (size_t)t * B,
                               p_gh, p_h, p_hsplit, p_encpad + (size_t)t * H);
    }
    transpose_encpad<<<(H * LP + 255) / 256, 256>>>();

    // ---- decoder ----
    // preamble combo: gh_0 + attn_0 from h_final (logits slot garbage, unread)
    launch_tc(NCOMBO, p_hsplit, p_wcombo, 1, p_gh, p_attnsc, p_logits,
              p_cbias, nullptr, nullptr, 0, nullptr);
    for (int t = 0; t < L; t++) {
        const int* tok = (t == 0) ? nullptr : target + (size_t)(t - 1) * B;
        softmax_attn<<<B / 8, 256>>>(p_attnsc, p_attn_tab, tok, BOS, p_aw);
        launch_nt(nullptr, 0, p_aw, LP, p_encpadT, LP, B, H, LP, nullptr, p_ctxsplit);
        launch_tc(H, p_ctxsplit, p_wx, 2, nullptr, nullptr, nullptr,
                  nullptr, p_comb_tab, tok, BOS, p_xsplit);
        launch_tc(H3, p_xsplit, p_wgi, 0, p_gi, nullptr, nullptr,
                  dec_bih, nullptr, nullptr, 0, nullptr);
        gru_gates<<<EW, 256>>>(p_gi, nullptr, nullptr, p_gh, p_h, p_hsplit, nullptr);
        launch_tc(NCOMBO, p_hsplit, p_wcombo, 1, p_gh, p_attnsc, p_logits,
                  p_cbias, nullptr, nullptr, 0, nullptr);
        out_gold<<<B / 8, 256>>>(p_logits, target + (size_t)t * B, p_scores);
    }

    // ---- outputs: [scores (B)] then [encoder_outputs (B, L, H)] ----
    scores_out<<<16, 256>>>(out);
    bcast_out<<<dim3(82, B), 256>>>(out);
}

// round 6
// speedup vs baseline: 2.7696x; 1.2260x over previous
#include <cuda_runtime.h>
#include <cuda_fp16.h>
#include <math.h>
#include <stdint.h>

#define B 4096
#define H 512
#define H3 1536
#define L 41
#define V 128
#define BOS 2
#define KA 1024            /* A split: [Ah | Al] fp16 */
#define KW 1024            /* W split: [Wh | Wl] fp16 */
#define NCOMBO 1792        /* [gh 1536 | logits 128 | attn 41 | pad 87] */

// ====================== device scratch ======================
__device__ __align__(128) float g_h[B * H];
__device__ __align__(128) float g_gh[B * H3];
__device__ __align__(128) float g_gi[B * H3];
__device__ __align__(128) float g_attnsc[B * L];
__device__ __align__(128) float g_logits[B * V];
__device__ __align__(128) float g_encpad[L * H];
__device__ __align__(128) float g_PT[H * 48];
__device__ __align__(128) float g_enc_tab[V * H3];
__device__ __align__(128) float g_attn_tab[V * L];
__device__ __align__(128) float g_comb_tab[V * H];
__device__ __align__(128) float g_scores[B];
__device__ __align__(128) float g_combo_bias[NCOMBO];

__device__ __align__(128) __half g_hsplit[B * KA];
__device__ __align__(128) __half g_xsplit[B * KA];
__device__ __align__(128) __half g_w_enc[H3 * KW];
__device__ __align__(128) __half g_w_gi[H3 * KW];
__device__ __align__(128) __half g_w_combo[NCOMBO * KW];   /* pad rows stay 0 */

// ====================== asm helpers ======================
__device__ __forceinline__ uint32_t smem_u32(const void* p) {
    uint32_t a;
    asm("{ .reg .u64 t; cvta.to.shared.u64 t, %1; cvt.u32.u64 %0, t; }" : "=r"(a) : "l"(p));
    return a;
}
__device__ __forceinline__ void cp16(uint32_t s, const void* g) {
    asm volatile("cp.async.cg.shared.global [%0], [%1], 16;" :: "r"(s), "l"(g));
}
#define CP_COMMIT() asm volatile("cp.async.commit_group;" ::: "memory")
#define CP_WAIT1()  asm volatile("cp.async.wait_group 1;" ::: "memory")
#define CP_WAIT0()  asm volatile("cp.async.wait_group 0;" ::: "memory")
#define LDMX4(r0, r1, r2, r3, a) \
    asm volatile("ldmatrix.sync.aligned.m8n8.x4.shared.b16 {%0,%1,%2,%3}, [%4];" \
        : "=r"(r0), "=r"(r1), "=r"(r2), "=r"(r3) : "r"(a))
#define MMA16816(d, a, bb) \
    asm volatile("mma.sync.aligned.m16n8k16.row.col.f32.f16.f16.f32 " \
        "{%0,%1,%2,%3}, {%4,%5,%6,%7}, {%8,%9}, {%0,%1,%2,%3};" \
        : "+f"((d)[0]), "+f"((d)[1]), "+f"((d)[2]), "+f"((d)[3]) \
        : "r"((a)[0]), "r"((a)[1]), "r"((a)[2]), "r"((a)[3]), \
          "r"((bb)[0]), "r"((bb)[1]))

// ====================== fp16 3-segment HMMA GEMM ======================
// C = (Ah+Al)(Wh+Wl)^T - Al*Wl^T  (error ~2^-24), fp32 accum.
// Per base-K chunk of 64: load Wh,Wl (128 rows) + Ah,Al (64 rows) once,
// run 3 MMA passes (Ah*Wh, Ah*Wl, Al*Wh).
// BM=64, BN=128, 256 threads (8 warps 2m x 4n, warp tile 32x32), occupancy 2.
// mode 0: C0[m*N+n] = acc + bias[n]
// mode 1: combo: n<1536 gh->C0(+bias); n<1664 logits->C2(ld 128,+bias);
//         n<1705 attn->C1(ld 41); else drop (zero pad weight rows)
#define PITCH 144
#define TILE_W (128 * PITCH)       /* 18432 */
#define TILE_A (64 * PITCH)        /* 9216 */
#define STAGE (2 * TILE_W + 2 * TILE_A)   /* 55296: Wh | Wl | Ah | Al */
#define SMEM_F16 (2 * STAGE)       /* 110592 -> 2 CTAs / SM */

__global__ void __launch_bounds__(256, 2) gemm_f16(
    int N,
    const __half* __restrict__ A,
    const __half* __restrict__ W,
    int mode,
    float* __restrict__ C0, float* __restrict__ C1, float* __restrict__ C2,
    const float* __restrict__ bias)
{
    extern __shared__ __align__(128) char smem[];
    const uint32_t sb = smem_u32(smem);
    const int tid = threadIdx.x;
    const int lane = tid & 31;
    const int wid = tid >> 5;
    const int wm = wid >> 2;          // 0..1
    const int wn = wid & 3;           // 0..3
    const int bm = blockIdx.y * 64;
    const int bn = blockIdx.x * 128;

    auto load_tile = [&](int c) {
        const uint32_t st = sb + (c & 1) * STAGE;
        const size_t koff = (size_t)c * 64;
        // Wh, Wl: 128 rows x 8 16B-chunks each = 1024 cp16 -> 4 iters of 256
#pragma unroll
        for (int i = 0; i < 4; i++) {
            int idx = tid + i * 256;
            int row = idx >> 3, col = idx & 7;
            const __half* wr = W + (size_t)(bn + row) * KW + koff + col * 8;
            cp16(st + row * PITCH + col * 16, wr);                       // Wh
            cp16(st + TILE_W + row * PITCH + col * 16, wr + 512);        // Wl
        }
        // Ah, Al: 64 rows x 8 = 512 cp16 -> 2 iters
#pragma unroll
        for (int i = 0; i < 2; i++) {
            int idx = tid + i * 256;
            int row = idx >> 3, col = idx & 7;
            const __half* ar = A + (size_t)(bm + row) * KA + koff + col * 8;
            cp16(st + 2 * TILE_W + row * PITCH + col * 16, ar);          // Ah
            cp16(st + 2 * TILE_W + TILE_A + row * PITCH + col * 16, ar + 512); // Al
        }
        CP_COMMIT();
    };

    float acc[2][4][4];
#pragma unroll
    for (int i = 0; i < 2; i++)
#pragma unroll
        for (int j = 0; j < 4; j++)
#pragma unroll
            for (int k = 0; k < 4; k++) acc[i][j][k] = 0.f;

    const uint32_t rowsel = lane & 15;
    const uint32_t khalf = (uint32_t)(lane >> 4);

    load_tile(0);
    for (int c = 0; c < 8; c++) {
        if (c < 7) { load_tile(c + 1); CP_WAIT1(); }
        else       { CP_WAIT0(); }
        __syncthreads();

        const uint32_t st = sb + (c & 1) * STAGE;
        const uint32_t sWh = st + (wn * 32) * PITCH;
        const uint32_t sWl = st + TILE_W + (wn * 32) * PITCH;
        const uint32_t sAh = st + 2 * TILE_W + (wm * 32) * PITCH;
        const uint32_t sAl = st + 2 * TILE_W + TILE_A + (wm * 32) * PITCH;
#pragma unroll
        for (int k16 = 0; k16 < 4; k16++) {
            const uint32_t kb = k16 * 32 + khalf * 16;
            uint32_t bh[4][2], bl[4][2];
#pragma unroll
            for (int np = 0; np < 2; np++) {
                uint32_t r0, r1, r2, r3;
                LDMX4(r0, r1, r2, r3, sWh + (np * 16 + rowsel) * PITCH + kb);
                bh[np * 2][0] = r0; bh[np * 2 + 1][0] = r1;
                bh[np * 2][1] = r2; bh[np * 2 + 1][1] = r3;
                LDMX4(r0, r1, r2, r3, sWl + (np * 16 + rowsel) * PITCH + kb);
                bl[np * 2][0] = r0; bl[np * 2 + 1][0] = r1;
                bl[np * 2][1] = r2; bl[np * 2 + 1][1] = r3;
            }
            uint32_t ah[2][4], al[2][4];
#pragma unroll
            for (int mi = 0; mi < 2; mi++) {
                LDMX4(ah[mi][0], ah[mi][1], ah[mi][2], ah[mi][3],
                      sAh + (mi * 16 + rowsel) * PITCH + kb);
                LDMX4(al[mi][0], al[mi][1], al[mi][2], al[mi][3],
                      sAl + (mi * 16 + rowsel) * PITCH + kb);
            }
#pragma unroll
            for (int mi = 0; mi < 2; mi++)
#pragma unroll
                for (int ni = 0; ni < 4; ni++) {
                    MMA16816(acc[mi][ni], ah[mi], bh[ni]);
                    MMA16816(acc[mi][ni], ah[mi], bl[ni]);
                    MMA16816(acc[mi][ni], al[mi], bh[ni]);
                }
        }
        __syncthreads();
    }

    // epilogue
    const int qr = lane >> 2;
    const int qc = (lane & 3) * 2;
#pragma unroll
    for (int mi = 0; mi < 2; mi++) {
        const size_t m0 = (size_t)(bm + wm * 32 + mi * 16 + qr);
        const size_t m1 = m0 + 8;
#pragma unroll
        for (int ni = 0; ni < 4; ni++) {
            const int n0 = bn + wn * 32 + ni * 8 + qc;
            float* a4 = acc[mi][ni];
#pragma unroll
            for (int e = 0; e < 4; e++) {
                const size_t m = (e < 2) ? m0 : m1;
                const int n = n0 + (e & 1);
                float v = a4[e] + bias[n];
                if (mode == 0) {
                    C0[m * N + n] = v;
                } else {
                    if (n < 1536)      C0[m * 1536 + n] = v;
                    else if (n < 1664) C2[m * 128 + (n - 1536)] = v;
                    else if (n < 1705) C1[m * 41 + (n - 1664)] = v;
                }
            }
        }
    }
}

// ====================== fp32 SIMT GEMM (prep tables + PT) ======================
__global__ void __launch_bounds__(256) gemm_nt(
    int M, int N, int K,
    const float* __restrict__ A, int lda,
    const float* __restrict__ W, int ldw,
    float* __restrict__ C, int ldc,
    const float* __restrict__ bias)
{
    __shared__ float As[16][128];
    __shared__ float Ws[16][64];
    const int bm = blockIdx.y * 128;
    const int bn = blockIdx.x * 64;
    const int tid = threadIdx.x;
    const int tx = tid & 15;
    const int ty = tid >> 4;

    float acc[8][4];
#pragma unroll
    for (int i = 0; i < 8; i++)
#pragma unroll
        for (int j = 0; j < 4; j++) acc[i][j] = 0.f;

    for (int k0 = 0; k0 < K; k0 += 16) {
#pragma unroll
        for (int i = 0; i < 2; i++) {
            int flat = tid + i * 256;
            int r = flat >> 2;
            int c4 = (flat & 3) << 2;
            float4 v = *reinterpret_cast<const float4*>(A + (size_t)(bm + r) * lda + k0 + c4);
            As[c4 + 0][r] = v.x; As[c4 + 1][r] = v.y;
            As[c4 + 2][r] = v.z; As[c4 + 3][r] = v.w;
        }
        {
            int r = tid >> 2;
            int c4 = (tid & 3) << 2;
            float4 v = make_float4(0.f, 0.f, 0.f, 0.f);
            if (bn + r < N)
                v = *reinterpret_cast<const float4*>(W + (size_t)(bn + r) * ldw + k0 + c4);
            Ws[c4 + 0][r] = v.x; Ws[c4 + 1][r] = v.y;
            Ws[c4 + 2][r] = v.z; Ws[c4 + 3][r] = v.w;
        }
        __syncthreads();
#pragma unroll
        for (int k = 0; k < 16; k++) {
            float4 a0 = *reinterpret_cast<const float4*>(&As[k][ty * 8]);
            float4 a1 = *reinterpret_cast<const float4*>(&As[k][ty * 8 + 4]);
            float4 w0 = *reinterpret_cast<const float4*>(&Ws[k][tx * 4]);
            float a[8] = {a0.x, a0.y, a0.z, a0.w, a1.x, a1.y, a1.z, a1.w};
            float w[4] = {w0.x, w0.y, w0.z, w0.w};
#pragma unroll
            for (int i = 0; i < 8; i++)
#pragma unroll
                for (int j = 0; j < 4; j++) acc[i][j] += a[i] * w[j];
        }
        __syncthreads();
    }

#pragma unroll
    for (int i = 0; i < 8; i++) {
        size_t m = (size_t)(bm + ty * 8 + i);
#pragma unroll
        for (int j = 0; j < 4; j++) {
            int n = bn + tx * 4 + j;
            if (n < N) {
                float v = acc[i][j];
                if (bias) v += bias[n];
                C[m * ldc + n] = v;
            }
        }
    }
}

// ====================== elementwise / fused small kernels ======================
__device__ __forceinline__ float sigmoidf_(float x) { return 1.f / (1.f + __expf(-x)); }

__global__ void gru_gates(const float* __restrict__ gi,
                          const float* __restrict__ giTab,
                          const int* __restrict__ tokRow,
                          const float* __restrict__ gh,
                          float* __restrict__ h,
                          __half* __restrict__ hsplit,
                          float* __restrict__ encRow)
{
    int i = blockIdx.x * blockDim.x + threadIdx.x;
    if (i >= B * H) return;
    int b = i >> 9, j = i & 511;
    float gir, giz, gin;
    if (giTab) {
        int t = tokRow[b];
        const float* p = giTab + (size_t)t * H3;
        gir = p[j]; giz = p[H + j]; gin = p[2 * H + j];
    } else {
        const float* p = gi + (size_t)b * H3;
        gir = p[j]; giz = p[H + j]; gin = p[2 * H + j];
    }
    const float* q = gh + (size_t)b * H3;
    float r = sigmoidf_(gir + q[j]);
    float z = sigmoidf_(giz + q[H + j]);
    float n = tanhf(gin + r * q[2 * H + j]);
    float hv = h[i];
    float hn = (1.f - z) * n + z * hv;
    h[i] = hn;
    __half hi = __float2half_rn(hn);
    __half lo = __float2half_rn(hn - __half2float(hi));
    size_t base = (size_t)b * KA + j;
    hsplit[base] = hi; hsplit[base + 512] = lo;
    if (encRow && b == 0) encRow[j] = hn;
}

// fused: attention softmax + x = relu(comb_tab[tok] + aw @ PT^T) + fp16 split
#define SXP 132
#define SMEM_SX (2 * 48 * SXP * 4 + 128 * 4)
__global__ void __launch_bounds__(256) softmax_x(
    const float* __restrict__ attnsc,
    const float* __restrict__ attn_tab,
    const int* __restrict__ tok, int defTok,
    const float* __restrict__ PT,          // [512, 48]
    const float* __restrict__ comb_tab,    // [V, 512]
    __half* __restrict__ xsplit)           // [B, 1024]
{
    extern __shared__ __align__(16) char smraw[];
    float* awT = reinterpret_cast<float*>(smraw);            // [48][132]
    float* PTt = awT + 48 * SXP;                             // [48][132]
    int* toks = reinterpret_cast<int*>(PTt + 48 * SXP);      // [128]
    const int tid = threadIdx.x;
    const int rb = blockIdx.y * 128;
    const int nb = blockIdx.x * 128;

#pragma unroll
    for (int i = 0; i < 6; i++) {
        int idx = tid + i * 256;
        int row = idx / 12, c4 = idx % 12;
        float4 v = *reinterpret_cast<const float4*>(PT + (size_t)(nb + row) * 48 + c4 * 4);
        PTt[(c4 * 4 + 0) * SXP + row] = v.x;
        PTt[(c4 * 4 + 1) * SXP + row] = v.y;
        PTt[(c4 * 4 + 2) * SXP + row] = v.z;
        PTt[(c4 * 4 + 3) * SXP + row] = v.w;
    }
    if (tid < 128) {
        int m = rb + tid;
        int tk = tok ? tok[m] : defTok;
        toks[tid] = tk;
        const float* sc = attnsc + (size_t)m * L;
        const float* tb = attn_tab + (size_t)tk * L;
        float mx = -1e30f;
        for (int l = 0; l < L; l++) {
            float v = sc[l] + tb[l];
            awT[l * SXP + tid] = v;
            mx = fmaxf(mx, v);
        }
        float s = 0.f;
        for (int l = 0; l < L; l++) {
            float e = __expf(awT[l * SXP + tid] - mx);
            awT[l * SXP + tid] = e;
            s += e;
        }
        float inv = 1.f / s;
        for (int l = 0; l < L; l++) awT[l * SXP + tid] *= inv;
        for (int l = L; l < 48; l++) awT[l * SXP + tid] = 0.f;
    }
    __syncthreads();

    const int ty = tid >> 4;
    const int tx = tid & 15;
    float acc[8][8];
#pragma unroll
    for (int i = 0; i < 8; i++)
#pragma unroll
        for (int j = 0; j < 8; j++) acc[i][j] = 0.f;

    for (int k = 0; k < 48; k++) {
        float4 a0 = *reinterpret_cast<const float4*>(awT + k * SXP + ty * 8);
        float4 a1 = *reinterpret_cast<const float4*>(awT + k * SXP + ty * 8 + 4);
        float4 b0 = *reinterpret_cast<const float4*>(PTt + k * SXP + tx * 8);
        float4 b1 = *reinterpret_cast<const float4*>(PTt + k * SXP + tx * 8 + 4);
        float a[8] = {a0.x, a0.y, a0.z, a0.w, a1.x, a1.y, a1.z, a1.w};
        float bb[8] = {b0.x, b0.y, b0.z, b0.w, b1.x, b1.y, b1.z, b1.w};
#pragma unroll
        for (int i = 0; i < 8; i++)
#pragma unroll
            for (int j = 0; j < 8; j++) acc[i][j] += a[i] * bb[j];
    }

#pragma unroll
    for (int i = 0; i < 8; i++) {
        size_t m = (size_t)(rb + ty * 8 + i);
        const float* tb = comb_tab + (size_t)toks[ty * 8 + i] * 512;
#pragma unroll
        for (int j = 0; j < 8; j++) {
            int n = nb + tx * 8 + j;
            float v = fmaxf(acc[i][j] + tb[n], 0.f);
            __half hi = __float2half_rn(v);
            __half lo = __float2half_rn(v - __half2float(hi));
            xsplit[m * KA + n] = hi;
            xsplit[m * KA + 512 + n] = lo;
        }
    }
}

__global__ void out_gold(const float* __restrict__ logits,
                         const int* __restrict__ tgtRow,
                         float* __restrict__ scores)
{
    int warp = (blockIdx.x * blockDim.x + threadIdx.x) >> 5;
    int lane = threadIdx.x & 31;
    if (warp >= B) return;
    const float* row = logits + (size_t)warp * V;
    float v[4];
    float mx = -1e30f;
#pragma unroll
    for (int i = 0; i < 4; i++) { v[i] = row[lane + 32 * i]; mx = fmaxf(mx, v[i]); }
#pragma unroll
    for (int o = 16; o > 0; o >>= 1) mx = fmaxf(mx, __shfl_xor_sync(~0u, mx, o));
    float s = 0.f;
#pragma unroll
    for (int i = 0; i < 4; i++) s += __expf(v[i] - mx);
#pragma unroll
    for (int o = 16; o > 0; o >>= 1) s += __shfl_xor_sync(~0u, s, o);
    if (lane == 0) {
        int tgt = tgtRow[warp];
        if (tgt != 0) scores[warp] += row[tgt] - (mx + logf(s));
    }
}

__global__ void init_h(const float* __restrict__ h0)
{
    int i = blockIdx.x * blockDim.x + threadIdx.x;
    if (i >= B * H) return;
    float v = h0[i];
    g_h[i] = v;
    int b = i >> 9, j = i & 511;
    __half hi = __float2half_rn(v);
    __half lo = __float2half_rn(v - __half2float(hi));
    size_t base = (size_t)b * KA + j;
    g_hsplit[base] = hi; g_hsplit[base + 512] = lo;
    if (i < B) g_scores[i] = 0.f;
}

// fp32 weights -> fp16 [Wh | Wl] rows of 1024
__global__ void split_w(__half* __restrict__ dst,
                        const float* __restrict__ src, int ldw, int colOff,
                        int rows, int dstRowOff)
{
    int i = blockIdx.x * blockDim.x + threadIdx.x;
    if (i >= rows * 512) return;
    int r = i >> 9, k = i & 511;
    float w = src[(size_t)r * ldw + colOff + k];
    __half hi = __float2half_rn(w);
    __half lo = __float2half_rn(w - __half2float(hi));
    size_t base = (size_t)(dstRowOff + r) * KW + k;
    dst[base] = hi; dst[base + 512] = lo;
}

__global__ void build_combo_bias(const float* __restrict__ bhh,
                                 const float* __restrict__ outb)
{
    int n = blockIdx.x * blockDim.x + threadIdx.x;
    if (n >= NCOMBO) return;
    g_combo_bias[n] = (n < 1536) ? bhh[n] : ((n < 1664) ? outb[n - 1536] : 0.f);
}

__global__ void scores_out(float* __restrict__ out)
{
    int i = blockIdx.x * blockDim.x + threadIdx.x;
    if (i < B) out[i] = g_scores[i];
}

__global__ void bcast_out(float* __restrict__ out)
{
    int idx = blockIdx.x * 256 + threadIdx.x;
    int b = blockIdx.y;
    out[(size_t)B + (size_t)b * (L * H) + idx] = g_encpad[idx];
}

// ====================== host ======================
static void launch_f16(int N, const __half* A, const __half* W, int mode,
                       float* C0, float* C1, float* C2, const float* bias)
{
    dim3 grid(N / 128, B / 64);
    gemm_f16<<<grid, 256, SMEM_F16>>>(N, A, W, mode, C0, C1, C2, bias);
}

extern "C" void kernel_launch(void* const* d_in, const int* in_sizes, int n_in,
                              void* d_out, int out_size)
{
    const int*   input   = (const int*)  d_in[0];
    const float* enc_h0  = (const float*)d_in[1];
    const int*   target  = (const int*)  d_in[2];
    const float* enc_emb = (const float*)d_in[3];
    const float* enc_Wih = (const float*)d_in[4];
    const float* enc_Whh = (const float*)d_in[5];
    const float* enc_bih = (const float*)d_in[6];
    const float* enc_bhh = (const float*)d_in[7];
    const float* dec_emb = (const float*)d_in[8];
    const float* attn_W  = (const float*)d_in[9];
    const float* attn_b  = (const float*)d_in[10];
    const float* comb_W  = (const float*)d_in[11];
    const float* comb_b  = (const float*)d_in[12];
    const float* dec_Wih = (const float*)d_in[13];
    const float* dec_Whh = (const float*)d_in[14];
    const float* dec_bih = (const float*)d_in[15];
    const float* dec_bhh = (const float*)d_in[16];
    const float* out_W   = (const float*)d_in[17];
    const float* out_b   = (const float*)d_in[18];
    float* out = (float*)d_out;

    cudaFuncSetAttribute(gemm_f16, cudaFuncAttributeMaxDynamicSharedMemorySize, SMEM_F16);
    cudaFuncSetAttribute(softmax_x, cudaFuncAttributeMaxDynamicSharedMemorySize, SMEM_SX);

    float *p_h, *p_gh, *p_gi, *p_attnsc, *p_logits, *p_encpad, *p_PT;
    float *p_enc_tab, *p_attn_tab, *p_comb_tab, *p_scores, *p_cbias;
    __half *p_hsplit, *p_xsplit, *p_wenc, *p_wgi, *p_wcombo;
    cudaGetSymbolAddress((void**)&p_h, g_h);
    cudaGetSymbolAddress((void**)&p_gh, g_gh);
    cudaGetSymbolAddress((void**)&p_gi, g_gi);
    cudaGetSymbolAddress((void**)&p_attnsc, g_attnsc);
    cudaGetSymbolAddress((void**)&p_logits, g_logits);
    cudaGetSymbolAddress((void**)&p_encpad, g_encpad);
    cudaGetSymbolAddress((void**)&p_PT, g_PT);
    cudaGetSymbolAddress((void**)&p_enc_tab, g_enc_tab);
    cudaGetSymbolAddress((void**)&p_attn_tab, g_attn_tab);
    cudaGetSymbolAddress((void**)&p_comb_tab, g_comb_tab);
    cudaGetSymbolAddress((void**)&p_scores, g_scores);
    cudaGetSymbolAddress((void**)&p_cbias, g_combo_bias);
    cudaGetSymbolAddress((void**)&p_hsplit, g_hsplit);
    cudaGetSymbolAddress((void**)&p_xsplit, g_xsplit);
    cudaGetSymbolAddress((void**)&p_wenc, g_w_enc);
    cudaGetSymbolAddress((void**)&p_wgi, g_w_gi);
    cudaGetSymbolAddress((void**)&p_wcombo, g_w_combo);

    const int EW = (B * H + 255) / 256;

    // ---- prep ----
    init_h<<<EW, 256>>>(enc_h0);
    gemm_nt<<<dim3(24, 1), 256>>>(V, H3, H, enc_emb, H, enc_Wih, H,
                                  p_enc_tab, H3, enc_bih);
    gemm_nt<<<dim3(1, 1), 256>>>(V, L, H, dec_emb, H, attn_W, 2 * H,
                                 p_attn_tab, L, attn_b);
    gemm_nt<<<dim3(8, 1), 256>>>(V, H, H, dec_emb, H, comb_W, 2 * H,
                                 p_comb_tab, H, comb_b);
    split_w<<<(H3 * 512 + 255) / 256, 256>>>(p_wenc, enc_Whh, H, 0, H3, 0);
    split_w<<<(H3 * 512 + 255) / 256, 256>>>(p_wgi, dec_Wih, H, 0, H3, 0);
    split_w<<<(H3 * 512 + 255) / 256, 256>>>(p_wcombo, dec_Whh, H, 0, H3, 0);
    split_w<<<(V * 512 + 255) / 256, 256>>>(p_wcombo, out_W, H, 0, V, 1536);
    split_w<<<(L * 512 + 255) / 256, 256>>>(p_wcombo, attn_W, 2 * H, H, L, 1664);
    build_combo_bias<<<(NCOMBO + 255) / 256, 256>>>(dec_bhh, out_b);

    // ---- encoder: 41 sequential GRU steps ----
    for (int t = 0; t < L; t++) {
        launch_f16(H3, p_hsplit, p_wenc, 0, p_gh, nullptr, nullptr, enc_bhh);
        gru_gates<<<EW, 256>>>(nullptr, p_enc_tab, input + (size_t)t * B,
                               p_gh, p_h, p_hsplit, p_encpad + (size_t)t * H);
    }

    // PT = comb_W[:, 512:] @ encpad^T  -> [512, 41] (ld 48)
    gemm_nt<<<dim3(1, 4), 256>>>(H, L, H, comb_W + H, 2 * H,
                                 p_encpad, H, p_PT, 48, nullptr);

    // ---- decoder ----
    launch_f16(NCOMBO, p_hsplit, p_wcombo, 1, p_gh, p_attnsc, p_logits, p_cbias);
    for (int t = 0; t < L; t++) {
        const int* tok = (t == 0) ? nullptr : target + (size_t)(t - 1) * B;
        softmax_x<<<dim3(4, 32), 256, SMEM_SX>>>(p_attnsc, p_attn_tab, tok, BOS,
                                                 p_PT, p_comb_tab, p_xsplit);
        launch_f16(H3, p_xsplit, p_wgi, 0, p_gi, nullptr, nullptr, dec_bih);
        gru_gates<<<EW, 256>>>(p_gi, nullptr, nullptr, p_gh, p_h, p_hsplit, nullptr);
        launch_f16(NCOMBO, p_hsplit, p_wcombo, 1, p_gh, p_attnsc, p_logits, p_cbias);
        out_gold<<<B / 8, 256>>>(p_logits, target + (size_t)t * B, p_scores);
    }

    // ---- outputs ----
    scores_out<<<16, 256>>>(out);
    bcast_out<<<dim3(82, B), 256>>>(out);
}

// round 7
// speedup vs baseline: 2.9528x; 1.0661x over previous
#include <cuda_runtime.h>
#include <cuda_fp16.h>
#include <math.h>
#include <stdint.h>

#define B 4096
#define H 512
#define H3 1536
#define L 41
#define V 128
#define BOS 2
#define KA 1024            /* A split: [Ah | Al] fp16 */
#define KW 1024            /* W split: [Wh | Wl] fp16 */
#define NCOMBO 1792        /* [gh 1536 | logits 128 | attn 41 | pad 87] */

// ====================== device scratch ======================
__device__ __align__(128) float g_h[B * H];
__device__ __align__(128) float g_gh[B * H3];
__device__ __align__(128) float g_gi[B * H3];
__device__ __align__(128) float g_aw[B * 48];
__device__ __align__(128) float g_encpad[L * H];
__device__ __align__(128) float g_PT[H * 48];          /* cols 41..47 stay 0 */
__device__ __align__(128) float g_enc_tab[V * H3];
__device__ __align__(128) float g_attn_tab[V * L];
__device__ __align__(128) float g_comb_tab[V * H];
__device__ __align__(128) float g_scores[B];
__device__ __align__(128) float g_combo_bias[NCOMBO];

__device__ __align__(128) __half g_hsplit[B * KA];
__device__ __align__(128) __half g_xsplit[B * KA];
__device__ __align__(128) __half g_w_enc[H3 * KW];
__device__ __align__(128) __half g_w_gi[H3 * KW];
__device__ __align__(128) __half g_w_combo[NCOMBO * KW];   /* pad rows stay 0 */

// ====================== asm helpers ======================
__device__ __forceinline__ uint32_t smem_u32(const void* p) {
    uint32_t a;
    asm("{ .reg .u64 t; cvta.to.shared.u64 t, %1; cvt.u32.u64 %0, t; }" : "=r"(a) : "l"(p));
    return a;
}
__device__ __forceinline__ void cp16(uint32_t s, const void* g) {
    asm volatile("cp.async.cg.shared.global [%0], [%1], 16;" :: "r"(s), "l"(g));
}
#define CP_COMMIT() asm volatile("cp.async.commit_group;" ::: "memory")
#define CP_WAIT1()  asm volatile("cp.async.wait_group 1;" ::: "memory")
#define CP_WAIT0()  asm volatile("cp.async.wait_group 0;" ::: "memory")
#define LDMX4(r0, r1, r2, r3, a) \
    asm volatile("ldmatrix.sync.aligned.m8n8.x4.shared.b16 {%0,%1,%2,%3}, [%4];" \
        : "=r"(r0), "=r"(r1), "=r"(r2), "=r"(r3) : "r"(a))
#define MMA16816(d, a, bb) \
    asm volatile("mma.sync.aligned.m16n8k16.row.col.f32.f16.f16.f32 " \
        "{%0,%1,%2,%3}, {%4,%5,%6,%7}, {%8,%9}, {%0,%1,%2,%3};" \
        : "+f"((d)[0]), "+f"((d)[1]), "+f"((d)[2]), "+f"((d)[3]) \
        : "r"((a)[0]), "r"((a)[1]), "r"((a)[2]), "r"((a)[3]), \
          "r"((bb)[0]), "r"((bb)[1]))

// ====================== fp16 3-segment HMMA GEMM ======================
// C = Ah*Wh + Ah*Wl + Al*Wh  (drops only Al*Wl ~2^-24), fp32 accum.
// BM=64, BN=128, 256 threads (8 warps 2m x 4n, warp tile 32x32), occ 2.
// mode 0: C0[m*N+n] = acc + bias[n]
// mode 1 (combo, N=1792):
//   bn<1536  : gh -> C0 (ld 1536, +bias)
//   bn==1536 : logits(128) -> fused logsumexp + gold accumulation into scores
//   bn==1664 : attn(41) -> fused softmax (incl attn_tab[tok]) -> awOut [B,48]
#define PITCH 144
#define TILE_W (128 * PITCH)       /* 18432 */
#define TILE_A (64 * PITCH)        /* 9216 */
#define STAGE (2 * TILE_W + 2 * TILE_A)   /* 55296 */
#define SMEM_F16 (2 * STAGE)       /* 110592 -> 2 CTAs / SM */

__global__ void __launch_bounds__(256, 2) gemm_f16(
    int N,
    const __half* __restrict__ A,
    const __half* __restrict__ W,
    int mode,
    float* __restrict__ C0,
    const float* __restrict__ bias,
    const float* __restrict__ attn_tab,
    const int* __restrict__ tgt,
    float* __restrict__ scores,
    float* __restrict__ awOut)
{
    extern __shared__ __align__(128) char smem[];
    const uint32_t sb = smem_u32(smem);
    const int tid = threadIdx.x;
    const int lane = tid & 31;
    const int wid = tid >> 5;
    const int wm = wid >> 2;          // 0..1
    const int wn = wid & 3;           // 0..3
    const int bm = blockIdx.y * 64;
    const int bn = blockIdx.x * 128;

    auto load_tile = [&](int c) {
        const uint32_t st = sb + (c & 1) * STAGE;
        const size_t koff = (size_t)c * 64;
#pragma unroll
        for (int i = 0; i < 4; i++) {
            int idx = tid + i * 256;
            int row = idx >> 3, col = idx & 7;
            const __half* wr = W + (size_t)(bn + row) * KW + koff + col * 8;
            cp16(st + row * PITCH + col * 16, wr);                       // Wh
            cp16(st + TILE_W + row * PITCH + col * 16, wr + 512);        // Wl
        }
#pragma unroll
        for (int i = 0; i < 2; i++) {
            int idx = tid + i * 256;
            int row = idx >> 3, col = idx & 7;
            const __half* ar = A + (size_t)(bm + row) * KA + koff + col * 8;
            cp16(st + 2 * TILE_W + row * PITCH + col * 16, ar);          // Ah
            cp16(st + 2 * TILE_W + TILE_A + row * PITCH + col * 16, ar + 512); // Al
        }
        CP_COMMIT();
    };

    float acc[2][4][4];
#pragma unroll
    for (int i = 0; i < 2; i++)
#pragma unroll
        for (int j = 0; j < 4; j++)
#pragma unroll
            for (int k = 0; k < 4; k++) acc[i][j][k] = 0.f;

    const uint32_t rowsel = lane & 15;
    const uint32_t khalf = (uint32_t)(lane >> 4);

    load_tile(0);
    for (int c = 0; c < 8; c++) {
        if (c < 7) { load_tile(c + 1); CP_WAIT1(); }
        else       { CP_WAIT0(); }
        __syncthreads();

        const uint32_t st = sb + (c & 1) * STAGE;
        const uint32_t sWh = st + (wn * 32) * PITCH;
        const uint32_t sWl = st + TILE_W + (wn * 32) * PITCH;
        const uint32_t sAh = st + 2 * TILE_W + (wm * 32) * PITCH;
        const uint32_t sAl = st + 2 * TILE_W + TILE_A + (wm * 32) * PITCH;
#pragma unroll
        for (int k16 = 0; k16 < 4; k16++) {
            const uint32_t kb = k16 * 32 + khalf * 16;
            uint32_t bh[4][2], bl[4][2];
#pragma unroll
            for (int np = 0; np < 2; np++) {
                uint32_t r0, r1, r2, r3;
                LDMX4(r0, r1, r2, r3, sWh + (np * 16 + rowsel) * PITCH + kb);
                bh[np * 2][0] = r0; bh[np * 2 + 1][0] = r1;
                bh[np * 2][1] = r2; bh[np * 2 + 1][1] = r3;
                LDMX4(r0, r1, r2, r3, sWl + (np * 16 + rowsel) * PITCH + kb);
                bl[np * 2][0] = r0; bl[np * 2 + 1][0] = r1;
                bl[np * 2][1] = r2; bl[np * 2 + 1][1] = r3;
            }
            uint32_t ah[2][4], al[2][4];
#pragma unroll
            for (int mi = 0; mi < 2; mi++) {
                LDMX4(ah[mi][0], ah[mi][1], ah[mi][2], ah[mi][3],
                      sAh + (mi * 16 + rowsel) * PITCH + kb);
                LDMX4(al[mi][0], al[mi][1], al[mi][2], al[mi][3],
                      sAl + (mi * 16 + rowsel) * PITCH + kb);
            }
#pragma unroll
            for (int mi = 0; mi < 2; mi++)
#pragma unroll
                for (int ni = 0; ni < 4; ni++) {
                    MMA16816(acc[mi][ni], ah[mi], bh[ni]);
                    MMA16816(acc[mi][ni], ah[mi], bl[ni]);
                    MMA16816(acc[mi][ni], al[mi], bh[ni]);
                }
        }
        __syncthreads();
    }

    // ---- epilogue ----
    const int qr = lane >> 2;
    const int qc = (lane & 3) * 2;
    const bool fused12 = (mode == 1) && (bn == 1536);
    const bool fused13 = (mode == 1) && (bn == 1664);

    if (!fused12 && !fused13) {
        const int ldc = (mode == 1) ? 1536 : N;
#pragma unroll
        for (int mi = 0; mi < 2; mi++) {
            const size_t m0 = (size_t)(bm + wm * 32 + mi * 16 + qr);
#pragma unroll
            for (int ni = 0; ni < 4; ni++) {
                const int n0 = bn + wn * 32 + ni * 8 + qc;
                float* a4 = acc[mi][ni];
                C0[m0 * ldc + n0]           = a4[0] + bias[n0];
                C0[m0 * ldc + n0 + 1]       = a4[1] + bias[n0 + 1];
                C0[(m0 + 8) * ldc + n0]     = a4[2] + bias[n0];
                C0[(m0 + 8) * ldc + n0 + 1] = a4[3] + bias[n0 + 1];
            }
        }
        return;
    }

    float* ep = reinterpret_cast<float*>(smem);
    const int pit = fused12 ? 129 : 49;
#pragma unroll
    for (int mi = 0; mi < 2; mi++) {
        const int r0 = wm * 32 + mi * 16 + qr;
#pragma unroll
        for (int ni = 0; ni < 4; ni++) {
            const int c0 = wn * 32 + ni * 8 + qc;
            float* a4 = acc[mi][ni];
#pragma unroll
            for (int e = 0; e < 4; e++) {
                const int r = r0 + ((e >= 2) ? 8 : 0);
                const int cc = c0 + (e & 1);
                float v = a4[e] + bias[bn + cc];
                if (fused12) ep[r * 129 + cc] = v;
                else if (cc < 41) ep[r * 49 + cc] = v;
            }
        }
    }
    __syncthreads();

    if (fused12) {
        if (tgt != nullptr) {
#pragma unroll
            for (int rr = 0; rr < 8; rr++) {
                const int row = wid * 8 + rr;
                const size_t m = (size_t)(bm + row);
                float x0 = ep[row * 129 + lane];
                float x1 = ep[row * 129 + lane + 32];
                float x2 = ep[row * 129 + lane + 64];
                float x3 = ep[row * 129 + lane + 96];
                float mx = fmaxf(fmaxf(x0, x1), fmaxf(x2, x3));
#pragma unroll
                for (int o = 16; o > 0; o >>= 1) mx = fmaxf(mx, __shfl_xor_sync(~0u, mx, o));
                float s = __expf(x0 - mx) + __expf(x1 - mx) + __expf(x2 - mx) + __expf(x3 - mx);
#pragma unroll
                for (int o = 16; o > 0; o >>= 1) s += __shfl_xor_sync(~0u, s, o);
                if (lane == 0) {
                    int tg = tgt[m];
                    if (tg != 0) scores[m] += ep[row * 129 + tg] - (mx + logf(s));
                }
            }
        }
    } else {
        // softmax over 41 attn logits per row (3 smem passes; no big reg arrays)
        if (tid < 64) {
            const size_t m = (size_t)(bm + tid);
            int tk = tgt ? tgt[m] : BOS;
            const float* tb = attn_tab + (size_t)tk * L;
            float* row = ep + tid * 49;
            float mx = -1e30f;
            for (int l = 0; l < L; l++) {
                float v = row[l] + tb[l];
                row[l] = v;
                mx = fmaxf(mx, v);
            }
            float s = 0.f;
            for (int l = 0; l < L; l++) {
                float e = __expf(row[l] - mx);
                row[l] = e;
                s += e;
            }
            float inv = 1.f / s;
            for (int l = 0; l < L; l++) row[l] *= inv;
            for (int l = L; l < 48; l++) row[l] = 0.f;
        }
        __syncthreads();
        for (int i = tid; i < 64 * 48; i += 256) {
            int r = i / 48, c = i - r * 48;
            awOut[(size_t)(bm + r) * 48 + c] = ep[r * 49 + c];
        }
    }
}

// ====================== fp32 SIMT GEMM (prep tables + PT) ======================
__global__ void __launch_bounds__(256) gemm_nt(
    int M, int N, int K,
    const float* __restrict__ A, int lda,
    const float* __restrict__ W, int ldw,
    float* __restrict__ C, int ldc,
    const float* __restrict__ bias)
{
    __shared__ float As[16][128];
    __shared__ float Ws[16][64];
    const int bm = blockIdx.y * 128;
    const int bn = blockIdx.x * 64;
    const int tid = threadIdx.x;
    const int tx = tid & 15;
    const int ty = tid >> 4;

    float acc[8][4];
#pragma unroll
    for (int i = 0; i < 8; i++)
#pragma unroll
        for (int j = 0; j < 4; j++) acc[i][j] = 0.f;

    for (int k0 = 0; k0 < K; k0 += 16) {
#pragma unroll
        for (int i = 0; i < 2; i++) {
            int flat = tid + i * 256;
            int r = flat >> 2;
            int c4 = (flat & 3) << 2;
            float4 v = *reinterpret_cast<const float4*>(A + (size_t)(bm + r) * lda + k0 + c4);
            As[c4 + 0][r] = v.x; As[c4 + 1][r] = v.y;
            As[c4 + 2][r] = v.z; As[c4 + 3][r] = v.w;
        }
        {
            int r = tid >> 2;
            int c4 = (tid & 3) << 2;
            float4 v = make_float4(0.f, 0.f, 0.f, 0.f);
            if (bn + r < N)
                v = *reinterpret_cast<const float4*>(W + (size_t)(bn + r) * ldw + k0 + c4);
            Ws[c4 + 0][r] = v.x; Ws[c4 + 1][r] = v.y;
            Ws[c4 + 2][r] = v.z; Ws[c4 + 3][r] = v.w;
        }
        __syncthreads();
#pragma unroll
        for (int k = 0; k < 16; k++) {
            float4 a0 = *reinterpret_cast<const float4*>(&As[k][ty * 8]);
            float4 a1 = *reinterpret_cast<const float4*>(&As[k][ty * 8 + 4]);
            float4 w0 = *reinterpret_cast<const float4*>(&Ws[k][tx * 4]);
            float a[8] = {a0.x, a0.y, a0.z, a0.w, a1.x, a1.y, a1.z, a1.w};
            float w[4] = {w0.x, w0.y, w0.z, w0.w};
#pragma unroll
            for (int i = 0; i < 8; i++)
#pragma unroll
                for (int j = 0; j < 4; j++) acc[i][j] += a[i] * w[j];
        }
        __syncthreads();
    }

#pragma unroll
    for (int i = 0; i < 8; i++) {
        size_t m = (size_t)(bm + ty * 8 + i);
#pragma unroll
        for (int j = 0; j < 4; j++) {
            int n = bn + tx * 4 + j;
            if (n < N) {
                float v = acc[i][j];
                if (bias) v += bias[n];
                C[m * ldc + n] = v;
            }
        }
    }
}

// ====================== elementwise / fused small kernels ======================
__device__ __forceinline__ float sigmoidf_(float x) { return 1.f / (1.f + __expf(-x)); }

// float2-vectorized GRU gates; grid 4096 x 256 (2 elems/thread)
__global__ void gru_gates(const float* __restrict__ gi,
                          const float* __restrict__ giTab,
                          const int* __restrict__ tokRow,
                          const float* __restrict__ gh,
                          float* __restrict__ h,
                          __half2* __restrict__ hsplit,
                          float* __restrict__ encRow)
{
    int i = blockIdx.x * blockDim.x + threadIdx.x;   // < B*H/2
    int b = i >> 8;
    int j = (i & 255) << 1;
    const float* p;
    if (giTab) p = giTab + (size_t)tokRow[b] * H3;
    else       p = gi + (size_t)b * H3;
    float2 gir = *reinterpret_cast<const float2*>(p + j);
    float2 giz = *reinterpret_cast<const float2*>(p + H + j);
    float2 gin = *reinterpret_cast<const float2*>(p + 2 * H + j);
    const float* q = gh + (size_t)b * H3;
    float2 qr = *reinterpret_cast<const float2*>(q + j);
    float2 qz = *reinterpret_cast<const float2*>(q + H + j);
    float2 qn = *reinterpret_cast<const float2*>(q + 2 * H + j);
    float2 hv = *reinterpret_cast<const float2*>(h + (size_t)b * H + j);

    float r0 = sigmoidf_(gir.x + qr.x), r1 = sigmoidf_(gir.y + qr.y);
    float z0 = sigmoidf_(giz.x + qz.x), z1 = sigmoidf_(giz.y + qz.y);
    float n0 = tanhf(gin.x + r0 * qn.x), n1 = tanhf(gin.y + r1 * qn.y);
    float h0 = (1.f - z0) * n0 + z0 * hv.x;
    float h1 = (1.f - z1) * n1 + z1 * hv.y;

    *reinterpret_cast<float2*>(h + (size_t)b * H + j) = make_float2(h0, h1);
    __half hh0 = __float2half_rn(h0), hh1 = __float2half_rn(h1);
    __half hl0 = __float2half_rn(h0 - __half2float(hh0));
    __half hl1 = __float2half_rn(h1 - __half2float(hh1));
    size_t base = ((size_t)b * KA + j) >> 1;
    hsplit[base] = __halves2half2(hh0, hh1);
    hsplit[base + 256] = __halves2half2(hl0, hl1);
    if (encRow && b == 0)
        *reinterpret_cast<float2*>(encRow + j) = make_float2(h0, h1);
}

// x = relu(comb_tab[tok] + aw @ PT^T) + fp16 split; K=48 fp32
#define SXP 132
#define SMEM_SX (2 * 48 * SXP * 4 + 128 * 4)
__global__ void __launch_bounds__(256) x_gemm(
    const float* __restrict__ aw,          // [B, 48] normalized, zero padded
    const int* __restrict__ tok, int defTok,
    const float* __restrict__ PT,          // [512, 48]
    const float* __restrict__ comb_tab,    // [V, 512]
    __half* __restrict__ xsplit)           // [B, 1024]
{
    extern __shared__ __align__(16) char smraw[];
    float* awT = reinterpret_cast<float*>(smraw);            // [48][132]
    float* PTt = awT + 48 * SXP;                             // [48][132]
    int* toks = reinterpret_cast<int*>(PTt + 48 * SXP);      // [128]
    const int tid = threadIdx.x;
    const int rb = blockIdx.y * 128;
    const int nb = blockIdx.x * 128;

#pragma unroll
    for (int i = 0; i < 6; i++) {
        int idx = tid + i * 256;
        int row = idx / 12, c4 = idx % 12;
        float4 v = *reinterpret_cast<const float4*>(PT + (size_t)(nb + row) * 48 + c4 * 4);
        PTt[(c4 * 4 + 0) * SXP + row] = v.x;
        PTt[(c4 * 4 + 1) * SXP + row] = v.y;
        PTt[(c4 * 4 + 2) * SXP + row] = v.z;
        PTt[(c4 * 4 + 3) * SXP + row] = v.w;
        float4 u = *reinterpret_cast<const float4*>(aw + (size_t)(rb + row) * 48 + c4 * 4);
        awT[(c4 * 4 + 0) * SXP + row] = u.x;
        awT[(c4 * 4 + 1) * SXP + row] = u.y;
        awT[(c4 * 4 + 2) * SXP + row] = u.z;
        awT[(c4 * 4 + 3) * SXP + row] = u.w;
    }
    if (tid < 128) toks[tid] = tok ? tok[rb + tid] : defTok;
    __syncthreads();

    const int ty = tid >> 4;
    const int tx = tid & 15;
    float acc[8][8];
#pragma unroll
    for (int i = 0; i < 8; i++)
#pragma unroll
        for (int j = 0; j < 8; j++) acc[i][j] = 0.f;

    for (int k = 0; k < 48; k++) {
        float4 a0 = *reinterpret_cast<const float4*>(awT + k * SXP + ty * 8);
        float4 a1 = *reinterpret_cast<const float4*>(awT + k * SXP + ty * 8 + 4);
        float4 b0 = *reinterpret_cast<const float4*>(PTt + k * SXP + tx * 8);
        float4 b1 = *reinterpret_cast<const float4*>(PTt + k * SXP + tx * 8 + 4);
        float a[8] = {a0.x, a0.y, a0.z, a0.w, a1.x, a1.y, a1.z, a1.w};
        float bb[8] = {b0.x, b0.y, b0.z, b0.w, b1.x, b1.y, b1.z, b1.w};
#pragma unroll
        for (int i = 0; i < 8; i++)
#pragma unroll
            for (int j = 0; j < 8; j++) acc[i][j] += a[i] * bb[j];
    }

#pragma unroll
    for (int i = 0; i < 8; i++) {
        size_t m = (size_t)(rb + ty * 8 + i);
        const float* tb = comb_tab + (size_t)toks[ty * 8 + i] * 512;
#pragma unroll
        for (int j = 0; j < 8; j++) {
            int n = nb + tx * 8 + j;
            float v = fmaxf(acc[i][j] + tb[n], 0.f);
            __half hi = __float2half_rn(v);
            __half lo = __float2half_rn(v - __half2float(hi));
            xsplit[m * KA + n] = hi;
            xsplit[m * KA + 512 + n] = lo;
        }
    }
}

__global__ void init_h(const float* __restrict__ h0)
{
    int i = blockIdx.x * blockDim.x + threadIdx.x;
    if (i >= B * H) return;
    float v = h0[i];
    g_h[i] = v;
    int b = i >> 9, j = i & 511;
    __half hi = __float2half_rn(v);
    __half lo = __float2half_rn(v - __half2float(hi));
    size_t base = (size_t)b * KA + j;
    g_hsplit[base] = hi; g_hsplit[base + 512] = lo;
    if (i < B) g_scores[i] = 0.f;
}

// fp32 weights -> fp16 [Wh | Wl] rows of 1024
__global__ void split_w(__half* __restrict__ dst,
                        const float* __restrict__ src, int ldw, int colOff,
                        int rows, int dstRowOff)
{
    int i = blockIdx.x * blockDim.x + threadIdx.x;
    if (i >= rows * 512) return;
    int r = i >> 9, k = i & 511;
    float w = src[(size_t)r * ldw + colOff + k];
    __half hi = __float2half_rn(w);
    __half lo = __float2half_rn(w - __half2float(hi));
    size_t base = (size_t)(dstRowOff + r) * KW + k;
    dst[base] = hi; dst[base + 512] = lo;
}

__global__ void build_combo_bias(const float* __restrict__ bhh,
                                 const float* __restrict__ outb)
{
    int n = blockIdx.x * blockDim.x + threadIdx.x;
    if (n >= NCOMBO) return;
    g_combo_bias[n] = (n < 1536) ? bhh[n] : ((n < 1664) ? outb[n - 1536] : 0.f);
}

__global__ void scores_out(float* __restrict__ out)
{
    int i = blockIdx.x * blockDim.x + threadIdx.x;
    if (i < B) out[i] = g_scores[i];
}

// encoder_outputs broadcast: float4 writes, grid (21, B)
__global__ void bcast_out(float* __restrict__ out)
{
    int idx = blockIdx.x * 256 + threadIdx.x;   // float4 index, < 5248
    if (idx >= (L * H) / 4) return;
    int b = blockIdx.y;
    const float4* src = reinterpret_cast<const float4*>(g_encpad);
    float4* dst = reinterpret_cast<float4*>(out) + (B / 4) + (size_t)b * (L * H / 4);
    dst[idx] = src[idx];
}

// ====================== host ======================
extern "C" void kernel_launch(void* const* d_in, const int* in_sizes, int n_in,
                              void* d_out, int out_size)
{
    const int*   input   = (const int*)  d_in[0];
    const float* enc_h0  = (const float*)d_in[1];
    const int*   target  = (const int*)  d_in[2];
    const float* enc_emb = (const float*)d_in[3];
    const float* enc_Wih = (const float*)d_in[4];
    const float* enc_Whh = (const float*)d_in[5];
    const float* enc_bih = (const float*)d_in[6];
    const float* enc_bhh = (const float*)d_in[7];
    const float* dec_emb = (const float*)d_in[8];
    const float* attn_W  = (const float*)d_in[9];
    const float* attn_b  = (const float*)d_in[10];
    const float* comb_W  = (const float*)d_in[11];
    const float* comb_b  = (const float*)d_in[12];
    const float* dec_Wih = (const float*)d_in[13];
    const float* dec_Whh = (const float*)d_in[14];
    const float* dec_bih = (const float*)d_in[15];
    const float* dec_bhh = (const float*)d_in[16];
    const float* out_W   = (const float*)d_in[17];
    const float* out_b   = (const float*)d_in[18];
    float* out = (float*)d_out;

    cudaFuncSetAttribute(gemm_f16, cudaFuncAttributeMaxDynamicSharedMemorySize, SMEM_F16);
    cudaFuncSetAttribute(x_gemm, cudaFuncAttributeMaxDynamicSharedMemorySize, SMEM_SX);

    float *p_h, *p_gh, *p_gi, *p_aw, *p_encpad, *p_PT;
    float *p_enc_tab, *p_attn_tab, *p_comb_tab, *p_scores, *p_cbias;
    __half *p_hsplit, *p_xsplit, *p_wenc, *p_wgi, *p_wcombo;
    cudaGetSymbolAddress((void**)&p_h, g_h);
    cudaGetSymbolAddress((void**)&p_gh, g_gh);
    cudaGetSymbolAddress((void**)&p_gi, g_gi);
    cudaGetSymbolAddress((void**)&p_aw, g_aw);
    cudaGetSymbolAddress((void**)&p_encpad, g_encpad);
    cudaGetSymbolAddress((void**)&p_PT, g_PT);
    cudaGetSymbolAddress((void**)&p_enc_tab, g_enc_tab);
    cudaGetSymbolAddress((void**)&p_attn_tab, g_attn_tab);
    cudaGetSymbolAddress((void**)&p_comb_tab, g_comb_tab);
    cudaGetSymbolAddress((void**)&p_scores, g_scores);
    cudaGetSymbolAddress((void**)&p_cbias, g_combo_bias);
    cudaGetSymbolAddress((void**)&p_hsplit, g_hsplit);
    cudaGetSymbolAddress((void**)&p_xsplit, g_xsplit);
    cudaGetSymbolAddress((void**)&p_wenc, g_w_enc);
    cudaGetSymbolAddress((void**)&p_wgi, g_w_gi);
    cudaGetSymbolAddress((void**)&p_wcombo, g_w_combo);

    const int EW = (B * H + 255) / 256;
    const int GRU_GRID = (B * H / 2) / 256;

    // ---- prep (ordered so launch index 5 is the first gemm_f16 for ncu) ----
    init_h<<<EW, 256>>>(enc_h0);                                              // 0
    split_w<<<(H3 * 512 + 255) / 256, 256>>>(p_wenc, enc_Whh, H, 0, H3, 0);   // 1
    gemm_nt<<<dim3(24, 1), 256>>>(V, H3, H, enc_emb, H, enc_Wih, H,
                                  p_enc_tab, H3, enc_bih);                    // 2
    gemm_nt<<<dim3(1, 1), 256>>>(V, L, H, dec_emb, H, attn_W, 2 * H,
                                 p_attn_tab, L, attn_b);                      // 3
    gemm_nt<<<dim3(8, 1), 256>>>(V, H, H, dec_emb, H, comb_W, 2 * H,
                                 p_comb_tab, H, comb_b);                      // 4

    // ---- encoder t=0 (launch 5 = gemm_f16) ----
    gemm_f16<<<dim3(12, 64), 256, SMEM_F16>>>(H3, p_hsplit, p_wenc, 0, p_gh,
        enc_bhh, nullptr, nullptr, nullptr, nullptr);                          // 5
    gru_gates<<<GRU_GRID, 256>>>(nullptr, p_enc_tab, input,
                                 p_gh, p_h, (__half2*)p_hsplit, p_encpad);

    // remaining prep (independent of encoder state)
    split_w<<<(H3 * 512 + 255) / 256, 256>>>(p_wgi, dec_Wih, H, 0, H3, 0);
    split_w<<<(H3 * 512 + 255) / 256, 256>>>(p_wcombo, dec_Whh, H, 0, H3, 0);
    split_w<<<(V * 512 + 255) / 256, 256>>>(p_wcombo, out_W, H, 0, V, 1536);
    split_w<<<(L * 512 + 255) / 256, 256>>>(p_wcombo, attn_W, 2 * H, H, L, 1664);
    build_combo_bias<<<(NCOMBO + 255) / 256, 256>>>(dec_bhh, out_b);

    // ---- encoder t=1..40 ----
    for (int t = 1; t < L; t++) {
        gemm_f16<<<dim3(12, 64), 256, SMEM_F16>>>(H3, p_hsplit, p_wenc, 0, p_gh,
            enc_bhh, nullptr, nullptr, nullptr, nullptr);
        gru_gates<<<GRU_GRID, 256>>>(nullptr, p_enc_tab, input + (size_t)t * B,
                                     p_gh, p_h, (__half2*)p_hsplit,
                                     p_encpad + (size_t)t * H);
    }

    // PT = comb_W[:, 512:] @ encpad^T  -> [512, 41] (ld 48, cols 41..47 stay 0)
    gemm_nt<<<dim3(1, 4), 256>>>(H, L, H, comb_W + H, 2 * H,
                                 p_encpad, H, p_PT, 48, nullptr);

    // ---- decoder ----
    // preamble combo: gh(0) + aw(0) from h_final (tok=BOS, gold disabled)
    gemm_f16<<<dim3(14, 64), 256, SMEM_F16>>>(NCOMBO, p_hsplit, p_wcombo, 1,
        p_gh, p_cbias, p_attn_tab, nullptr, p_scores, p_aw);
    for (int t = 0; t < L; t++) {
        const int* tokPrev = (t == 0) ? nullptr : target + (size_t)(t - 1) * B;
        x_gemm<<<dim3(4, 32), 256, SMEM_SX>>>(p_aw, tokPrev, BOS,
                                              p_PT, p_comb_tab, p_xsplit);
        gemm_f16<<<dim3(12, 64), 256, SMEM_F16>>>(H3, p_xsplit, p_wgi, 0, p_gi,
            dec_bih, nullptr, nullptr, nullptr, nullptr);
        gru_gates<<<GRU_GRID, 256>>>(p_gi, nullptr, nullptr, p_gh, p_h,
                                     (__half2*)p_hsplit, nullptr);
        gemm_f16<<<dim3(14, 64), 256, SMEM_F16>>>(NCOMBO, p_hsplit, p_wcombo, 1,
            p_gh, p_cbias, p_attn_tab, target + (size_t)t * B, p_scores, p_aw);
    }

    // ---- outputs: [scores (B)] then [encoder_outputs (B, L, H)] ----
    scores_out<<<16, 256>>>(out);
    bcast_out<<<dim3(21, B), 256>>>(out);
}